// round 11
// baseline (speedup 1.0000x reference)
#include <cuda_runtime.h>
#include <cuda_bf16.h>
#include <math.h>

typedef unsigned int uint;
typedef __nv_bfloat16 bf16;

#define BB   64
#define DECL 12
#define FF   32
#define HH   512
#define EE   96
#define TT   4
#define G3   1536
#define NPRE 3584   /* 512 (query) + 1536 (gh0) + 1536 (gh1) */
#define KX0  544    /* F + H */
#define KOUT 1056   /* 2H + F */
#define NBLK 296    /* 2 CTAs per SM x 148 SMs */
#define SRB  72     /* bf16 smem plane row stride (conflict-free) */

// ---------------- fp32 scratch ----------------
__device__ __align__(16) float g_encproj[BB*EE*HH];   // 12.6 MB
__device__ __align__(16) float g_h0[BB*HH];
__device__ __align__(16) float g_h1[BB*HH];
__device__ __align__(16) float g_cur[BB*FF];
__device__ __align__(16) float g_pre[4][BB*NPRE];     // K-split x4 partials: query|gh0|gh1
__device__ __align__(16) float g_gi[8][BB*G3];        // K-split x8 partials for gi
__device__ __align__(16) float g_ws[BB*HH];
__device__ __align__(16) float g_sc[BB*EE];           // attention scores

// ---------------- bf16 hi/lo planes (split once, reused) ----------------
__device__ __align__(16) bf16 gb_encH[BB*EE*HH], gb_encL[BB*EE*HH];
__device__ __align__(16) bf16 gb_WaeH[HH*HH],    gb_WaeL[HH*HH];
__device__ __align__(16) bf16 gb_WahH[HH*HH],    gb_WahL[HH*HH];
__device__ __align__(16) bf16 gb_Wh0H[G3*HH],    gb_Wh0L[G3*HH];
__device__ __align__(16) bf16 gb_Wh1H[G3*HH],    gb_Wh1L[G3*HH];
__device__ __align__(16) bf16 gb_Wi0H[G3*KX0],   gb_Wi0L[G3*KX0];
__device__ __align__(16) bf16 gb_Wi1H[G3*HH],    gb_Wi1L[G3*HH];
__device__ __align__(16) bf16 gb_h0H[BB*HH],     gb_h0L[BB*HH];
__device__ __align__(16) bf16 gb_h1H[BB*HH],     gb_h1L[BB*HH];
__device__ __align__(16) bf16 gb_x0H[BB*KX0],    gb_x0L[BB*KX0];

__device__ unsigned g_bar_cnt = 0;
__device__ unsigned g_bar_gen = 0;

// ---------------- shared (per 256-thread CTA) ----------------
__shared__ __align__(16) bf16 sAH2[64*SRB];
__shared__ __align__(16) bf16 sAL2[64*SRB];
__shared__ __align__(16) bf16 sWH2[64*SRB];
__shared__ __align__(16) bf16 sWL2[64*SRB];
__shared__ __align__(16) float sBuf[1100];

// ---------------- helpers ----------------
__device__ __forceinline__ float fast_sigmoid(float x) {
    return 1.0f / (1.0f + __expf(-x));
}
__device__ __forceinline__ float fast_tanh(float x) {
    float e = __expf(-2.0f * fabsf(x));
    float t = (1.0f - e) / (1.0f + e);
    return copysignf(t, x);
}
__device__ __forceinline__ void split1(float x, bf16 &h, bf16 &l) {
    h = __float2bfloat16(x);
    l = __float2bfloat16(x - __bfloat162float(h));
}
__device__ __forceinline__ uint lds32b(const bf16* p, int r, int c) {
    return *reinterpret_cast<const uint*>(&p[r*SRB + c]);
}
__device__ __forceinline__ void mma16816(float* d, const uint* a, uint b0, uint b1) {
    asm volatile(
        "mma.sync.aligned.m16n8k16.row.col.f32.bf16.bf16.f32 "
        "{%0,%1,%2,%3},{%4,%5,%6,%7},{%8,%9},{%0,%1,%2,%3};"
        : "+f"(d[0]), "+f"(d[1]), "+f"(d[2]), "+f"(d[3])
        : "r"(a[0]), "r"(a[1]), "r"(a[2]), "r"(a[3]), "r"(b0), "r"(b1));
}

// grid barrier, 296 arrivals (all CTAs resident by __launch_bounds__(256,2))
__device__ __forceinline__ void gsync() {
    __syncthreads();
    if (threadIdx.x == 0) {
        __threadfence();
        unsigned gen = *((volatile unsigned*)&g_bar_gen);
        if (atomicAdd(&g_bar_cnt, 1u) == (unsigned)(NBLK - 1)) {
            g_bar_cnt = 0;
            __threadfence();
            *((volatile unsigned*)&g_bar_gen) = gen + 1u;
        } else {
            while (*((volatile unsigned*)&g_bar_gen) == gen) { }
        }
    }
    __syncthreads();
}

// ---------------- bf16x3 TC GEMM, 256 threads ----------------
// C[64][64] = A[64][klen] @ W[64][klen]^T ; klen % 32 == 0.
template<bool ACG>
__device__ __forceinline__ void gemm64b(
    const bf16* __restrict__ AH, const bf16* __restrict__ AL, int lda,
    const bf16* __restrict__ WH, const bf16* __restrict__ WL, int ldw,
    float* __restrict__ C, int ldc, int klen)
{
    const int tid  = threadIdx.x;
    const int warp = tid >> 5, lane = tid & 31;
    const int rt = warp >> 1, ct = warp & 1;        // warp tile: 16 rows x 32 cols
    const int g  = lane >> 2;
    const int q  = (lane & 3) << 1;
    const int srow = tid >> 2, scol = (tid & 3) << 4;  // 16 bf16 per plane per thread
    float d[4][4] = {};

    for (int k0 = 0; k0 < klen; k0 += 64) {
        const int rem = klen - k0;          // 64 or 32/96-tail
        #pragma unroll
        for (int c = 0; c < 16; c += 8) {
            if (scol + c < rem) {
                const int off = k0 + scol + c;
                uint4 vah = ACG ? __ldcg(reinterpret_cast<const uint4*>(&AH[srow*lda + off]))
                                : __ldg (reinterpret_cast<const uint4*>(&AH[srow*lda + off]));
                uint4 val = ACG ? __ldcg(reinterpret_cast<const uint4*>(&AL[srow*lda + off]))
                                : __ldg (reinterpret_cast<const uint4*>(&AL[srow*lda + off]));
                uint4 vwh = __ldg(reinterpret_cast<const uint4*>(&WH[srow*ldw + off]));
                uint4 vwl = __ldg(reinterpret_cast<const uint4*>(&WL[srow*ldw + off]));
                *reinterpret_cast<uint4*>(&sAH2[srow*SRB + scol + c]) = vah;
                *reinterpret_cast<uint4*>(&sAL2[srow*SRB + scol + c]) = val;
                *reinterpret_cast<uint4*>(&sWH2[srow*SRB + scol + c]) = vwh;
                *reinterpret_cast<uint4*>(&sWL2[srow*SRB + scol + c]) = vwl;
            }
        }
        __syncthreads();

        #pragma unroll
        for (int ks = 0; ks < 64; ks += 16) {
            if (ks < rem) {
                uint aH[4], aL[4];
                const int r0 = rt*16 + g;
                aH[0] = lds32b(sAH2, r0,     ks+q);   aH[1] = lds32b(sAH2, r0 + 8, ks+q);
                aH[2] = lds32b(sAH2, r0,     ks+q+8); aH[3] = lds32b(sAH2, r0 + 8, ks+q+8);
                aL[0] = lds32b(sAL2, r0,     ks+q);   aL[1] = lds32b(sAL2, r0 + 8, ks+q);
                aL[2] = lds32b(sAL2, r0,     ks+q+8); aL[3] = lds32b(sAL2, r0 + 8, ks+q+8);
                #pragma unroll
                for (int nt = 0; nt < 4; nt++) {
                    const int n0 = ct*32 + nt*8 + g;
                    uint bH0 = lds32b(sWH2, n0, ks+q), bH1 = lds32b(sWH2, n0, ks+q+8);
                    uint bL0 = lds32b(sWL2, n0, ks+q), bL1 = lds32b(sWL2, n0, ks+q+8);
                    mma16816(d[nt], aH, bH0, bH1);   // hi*hi
                    mma16816(d[nt], aH, bL0, bL1);   // hi*lo
                    mma16816(d[nt], aL, bH0, bH1);   // lo*hi
                }
            }
        }
        __syncthreads();
    }

    const int r0 = rt*16 + g;
    #pragma unroll
    for (int nt = 0; nt < 4; nt++) {
        const int c0 = ct*32 + nt*8 + q;
        __stcg(reinterpret_cast<float2*>(&C[r0*ldc + c0]),       make_float2(d[nt][0], d[nt][1]));
        __stcg(reinterpret_cast<float2*>(&C[(r0 + 8)*ldc + c0]), make_float2(d[nt][2], d[nt][3]));
    }
}

// ---------------- the whole decoder, persistent ----------------
__global__ __launch_bounds__(256, 2) void k_decoder(
    const float* __restrict__ inputs, const float* __restrict__ hidden,
    const float* __restrict__ enc,    const int* __restrict__ tind,
    const float* __restrict__ Wattn,  const float* __restrict__ b_attn,
    const float* __restrict__ v_attn,
    const float* __restrict__ Wi0, const float* __restrict__ Wh0,
    const float* __restrict__ bi0, const float* __restrict__ bh0,
    const float* __restrict__ Wi1, const float* __restrict__ Wh1,
    const float* __restrict__ bi1, const float* __restrict__ bh1,
    const float* __restrict__ W_out, const float* __restrict__ b_out,
    float* __restrict__ dout)
{
    const int bid  = blockIdx.x;
    const int tid  = threadIdx.x;
    const int warp = tid >> 5, lane = tid & 31;    // 8 warps
    const int gtid = bid*256 + tid;
    const int gstr = NBLK*256;

    // ===== init: copies + one-time bf16 splits =====
    for (int i = gtid; i < BB*HH; i += gstr) {
        float h0v = __ldg(&hidden[i]);
        float h1v = __ldg(&hidden[BB*HH + i]);
        __stcg(&g_h0[i], h0v);
        __stcg(&g_h1[i], h1v);
        bf16 hh, hl;
        split1(h0v, hh, hl); __stcg(&gb_h0H[i], hh); __stcg(&gb_h0L[i], hl);
        split1(h1v, hh, hl); __stcg(&gb_h1H[i], hh); __stcg(&gb_h1L[i], hl);
    }
    for (int i = gtid; i < BB*FF; i += gstr) {
        int b = i >> 5, f = i & 31;
        __stcg(&g_cur[i], __ldg(&inputs[b*DECL*FF + f]));
    }
    for (int i = gtid; i < BB*EE*HH; i += gstr) {
        bf16 h, l; split1(__ldg(&enc[i]), h, l);
        __stcg(&gb_encH[i], h); __stcg(&gb_encL[i], l);
    }
    for (int i = gtid; i < HH*HH; i += gstr) {
        int gg = i >> 9, k = i & 511;
        bf16 h, l;
        split1(__ldg(&Wattn[gg*(2*HH) + k]), h, l);
        __stcg(&gb_WahH[i], h); __stcg(&gb_WahL[i], l);
        split1(__ldg(&Wattn[gg*(2*HH) + HH + k]), h, l);
        __stcg(&gb_WaeH[i], h); __stcg(&gb_WaeL[i], l);
    }
    for (int i = gtid; i < G3*HH; i += gstr) {
        bf16 h, l;
        split1(__ldg(&Wh0[i]), h, l); __stcg(&gb_Wh0H[i], h); __stcg(&gb_Wh0L[i], l);
        split1(__ldg(&Wh1[i]), h, l); __stcg(&gb_Wh1H[i], h); __stcg(&gb_Wh1L[i], l);
        split1(__ldg(&Wi1[i]), h, l); __stcg(&gb_Wi1H[i], h); __stcg(&gb_Wi1L[i], l);
    }
    for (int i = gtid; i < G3*KX0; i += gstr) {
        bf16 h, l; split1(__ldg(&Wi0[i]), h, l);
        __stcg(&gb_Wi0H[i], h); __stcg(&gb_Wi0L[i], l);
    }
    gsync();

    // ===== phase E: enc_proj (96 M-tiles x 8 N-tiles, K=512) =====
    for (int it = bid; it < 96*8; it += NBLK) {
        int m = it >> 3, n = it & 7;
        gemm64b<false>(gb_encH + m*64*HH, gb_encL + m*64*HH, HH,
                       gb_WaeH + n*64*HH, gb_WaeL + n*64*HH, HH,
                       g_encproj + m*64*HH + n*64, HH, HH);
    }
    gsync();

    // ===== 12 decode steps =====
    for (int t = 0; t < DECL; t++) {
        // --- PA: query = h1 @ Wah^T : 8 N-tiles x Ksplit4(128) = 32 jobs
        for (int it = bid; it < 32; it += NBLK) {
            int col0 = (it >> 2) * 64;
            int s    = it & 3;
            int k0   = s * 128;
            gemm64b<true>(gb_h1H + k0, gb_h1L + k0, HH,
                          gb_WahH + col0*HH + k0, gb_WahL + col0*HH + k0, HH,
                          g_pre[s] + col0, NPRE, 128);
        }
        gsync();

        // --- PB: scores (768 jobs) || gh0/gh1 GEMMs (192 jobs) = 960 jobs
        for (int it = bid; it < 960; it += NBLK) {
            if (it < 768) {
                __syncthreads();
                int b = it / 12, part = it % 12;
                float* qs = sBuf;
                float* vs = sBuf + 512;
                #pragma unroll
                for (int ii = 0; ii < 2; ii++) {
                    int i = ii*256 + tid;
                    float qv = __ldg(&b_attn[i]);
                    #pragma unroll
                    for (int s = 0; s < 4; s++) qv += __ldcg(&g_pre[s][b*NPRE + i]);
                    qs[i] = qv;
                    vs[i] = __ldg(&v_attn[i]);
                }
                __syncthreads();
                int e = part*8 + warp;
                const float4* ep4 = reinterpret_cast<const float4*>(g_encproj + (b*EE + e)*HH);
                float ssum = 0.0f;
                #pragma unroll
                for (int i = 0; i < 4; i++) {
                    float4 v = __ldcg(&ep4[i*32 + lane]);
                    int gg = (i*32 + lane) * 4;
                    ssum += fast_tanh(v.x + qs[gg  ]) * vs[gg  ];
                    ssum += fast_tanh(v.y + qs[gg+1]) * vs[gg+1];
                    ssum += fast_tanh(v.z + qs[gg+2]) * vs[gg+2];
                    ssum += fast_tanh(v.w + qs[gg+3]) * vs[gg+3];
                }
                #pragma unroll
                for (int off = 16; off > 0; off >>= 1)
                    ssum += __shfl_xor_sync(0xffffffffu, ssum, off);
                if (lane == 0) __stcg(&g_sc[b*EE + e], ssum);
            } else {
                int jt = it - 768;                 // 0..191
                int col0 = 512 + (jt >> 2) * 64;   // gh0|gh1 columns 512..3583
                int s    = jt & 3;
                int k0   = s * 128;
                const bf16 *AH, *AL, *WH, *WL;
                if (col0 < 2048) {
                    AH = gb_h0H; AL = gb_h0L;
                    WH = gb_Wh0H + (col0-512)*HH; WL = gb_Wh0L + (col0-512)*HH;
                } else {
                    AH = gb_h1H; AL = gb_h1L;
                    WH = gb_Wh1H + (col0-2048)*HH; WL = gb_Wh1L + (col0-2048)*HH;
                }
                gemm64b<true>(AH + k0, AL + k0, HH, WH + k0, WL + k0, HH,
                              g_pre[s] + col0, NPRE, 128);
            }
        }
        gsync();

        // --- PC: softmax + ws + assemble x0 : 128 jobs (b, col-half)
        for (int it = bid; it < BB*2; it += NBLK) {
            __syncthreads();
            int b = it >> 1, jh = it & 1;
            float* sc = sBuf;
            if (warp == 0) {
                float s0 = __ldcg(&g_sc[b*EE + lane]);
                float s1 = __ldcg(&g_sc[b*EE + lane + 32]);
                float s2 = __ldcg(&g_sc[b*EE + lane + 64]);
                float m = fmaxf(s0, fmaxf(s1, s2));
                #pragma unroll
                for (int off = 16; off > 0; off >>= 1)
                    m = fmaxf(m, __shfl_xor_sync(0xffffffffu, m, off));
                float p0 = __expf(s0-m), p1 = __expf(s1-m), p2 = __expf(s2-m);
                float sum = p0 + p1 + p2;
                #pragma unroll
                for (int off = 16; off > 0; off >>= 1)
                    sum += __shfl_xor_sync(0xffffffffu, sum, off);
                float inv = 1.0f / sum;
                sc[lane] = p0*inv; sc[lane+32] = p1*inv; sc[lane+64] = p2*inv;
            }
            __syncthreads();
            int col = jh*256 + tid;
            float acc = 0.0f;
            const float* eb = enc + b*EE*HH + col;
            #pragma unroll 8
            for (int e = 0; e < EE; e++) acc += sc[e] * __ldg(&eb[e*HH]);
            __stcg(&g_ws[b*HH + col], acc);
            bf16 h, l; split1(acc, h, l);
            __stcg(&gb_x0H[b*KX0 + FF + col], h);
            __stcg(&gb_x0L[b*KX0 + FF + col], l);
            if (jh == 0 && tid < FF) {
                float cv = __ldcg(&g_cur[b*FF + tid]);
                split1(cv, h, l);
                __stcg(&gb_x0H[b*KX0 + tid], h);
                __stcg(&gb_x0L[b*KX0 + tid], l);
            }
        }
        gsync();

        // --- PD: gi0 = x0 @ Wi0^T : 24 N-tiles x Ksplit8 {96,64x7} = 192 jobs
        for (int it = bid; it < 192; it += NBLK) {
            int col0 = (it >> 3) * 64;
            int s    = it & 7;
            int k0   = (s == 0) ? 0 : (32 + s*64);
            int klen = (s == 0) ? 96 : 64;
            gemm64b<true>(gb_x0H + k0, gb_x0L + k0, KX0,
                          gb_Wi0H + col0*KX0 + k0, gb_Wi0L + col0*KX0 + k0, KX0,
                          g_gi[s] + col0, G3, klen);
        }
        gsync();

        // --- PE: GRU combine layer 0 -> h0 : 128 jobs (b, col-half)
        for (int it = bid; it < BB*2; it += NBLK) {
            int b = it >> 1;
            int j = (it & 1)*256 + tid;
            float ir = __ldg(&bi0[j]), iz = __ldg(&bi0[j+HH]), in_ = __ldg(&bi0[j+2*HH]);
            float hr = __ldg(&bh0[j]), hz = __ldg(&bh0[j+HH]), hn  = __ldg(&bh0[j+2*HH]);
            #pragma unroll
            for (int s = 0; s < 8; s++) {
                const float* gi = g_gi[s] + b*G3;
                ir += __ldcg(&gi[j]); iz += __ldcg(&gi[j+HH]); in_ += __ldcg(&gi[j+2*HH]);
            }
            #pragma unroll
            for (int s = 0; s < 4; s++) {
                const float* gh = g_pre[s] + b*NPRE + 512;
                hr += __ldcg(&gh[j]); hz += __ldcg(&gh[j+HH]); hn += __ldcg(&gh[j+2*HH]);
            }
            float r = fast_sigmoid(ir + hr);
            float z = fast_sigmoid(iz + hz);
            float n = fast_tanh(in_ + r * hn);
            float hp = __ldcg(&g_h0[b*HH + j]);
            float h0n = (1.0f - z)*n + z*hp;
            __stcg(&g_h0[b*HH + j], h0n);
            bf16 h, l; split1(h0n, h, l);
            __stcg(&gb_h0H[b*HH + j], h);
            __stcg(&gb_h0L[b*HH + j], l);
        }
        gsync();

        // --- PF: gi1 = h0_new @ Wi1^T : 24 N-tiles x Ksplit8(64) = 192 jobs
        for (int it = bid; it < 192; it += NBLK) {
            int col0 = (it >> 3) * 64;
            int s    = it & 7;
            int k0   = s * 64;
            gemm64b<true>(gb_h0H + k0, gb_h0L + k0, HH,
                          gb_Wi1H + col0*HH + k0, gb_Wi1L + col0*HH + k0, HH,
                          g_gi[s] + col0, G3, 64);
        }
        gsync();

        // --- PG: GRU combine layer 1 -> h1, fused out-proj + next cur : 64 jobs
        for (int it = bid; it < BB; it += NBLK) {
            __syncthreads();
            int b = it;
            float* ho  = sBuf;          // 512
            float* red = sBuf + 512;    // 32 + 4
            #pragma unroll
            for (int jj = 0; jj < 2; jj++) {
                int j = jj*256 + tid;
                float ir = __ldg(&bi1[j]), iz = __ldg(&bi1[j+HH]), in_ = __ldg(&bi1[j+2*HH]);
                float hr = __ldg(&bh1[j]), hz = __ldg(&bh1[j+HH]), hn  = __ldg(&bh1[j+2*HH]);
                #pragma unroll
                for (int s = 0; s < 8; s++) {
                    const float* gi = g_gi[s] + b*G3;
                    ir += __ldcg(&gi[j]); iz += __ldcg(&gi[j+HH]); in_ += __ldcg(&gi[j+2*HH]);
                }
                #pragma unroll
                for (int s = 0; s < 4; s++) {
                    const float* gh = g_pre[s] + b*NPRE + 2048;
                    hr += __ldcg(&gh[j]); hz += __ldcg(&gh[j+HH]); hn += __ldcg(&gh[j+2*HH]);
                }
                float r = fast_sigmoid(ir + hr);
                float z = fast_sigmoid(iz + hz);
                float n = fast_tanh(in_ + r * hn);
                float hp = __ldcg(&g_h1[b*HH + j]);
                float h1n = (1.0f - z)*n + z*hp;
                __stcg(&g_h1[b*HH + j], h1n);
                bf16 h, l; split1(h1n, h, l);
                __stcg(&gb_h1H[b*HH + j], h);
                __stcg(&gb_h1L[b*HH + j], l);
                ho[j] = h1n;
            }
            __syncthreads();

            float a0 = 0.f, a1 = 0.f, a2 = 0.f, a3 = 0.f;
            for (int k = tid; k < KOUT; k += 256) {
                float x;
                if (k < HH)          x = ho[k];
                else if (k < 2*HH)   x = __ldcg(&g_ws[b*HH + k - HH]);
                else                 x = __ldcg(&g_cur[b*FF + (k - 2*HH)]);
                a0 += x * __ldg(&W_out[k]);
                a1 += x * __ldg(&W_out[KOUT + k]);
                a2 += x * __ldg(&W_out[2*KOUT + k]);
                a3 += x * __ldg(&W_out[3*KOUT + k]);
            }
            #pragma unroll
            for (int off = 16; off > 0; off >>= 1) {
                a0 += __shfl_xor_sync(0xffffffffu, a0, off);
                a1 += __shfl_xor_sync(0xffffffffu, a1, off);
                a2 += __shfl_xor_sync(0xffffffffu, a2, off);
                a3 += __shfl_xor_sync(0xffffffffu, a3, off);
            }
            if (lane == 0) {
                red[0*8 + warp] = a0; red[1*8 + warp] = a1;
                red[2*8 + warp] = a2; red[3*8 + warp] = a3;
            }
            __syncthreads();
            if (tid < 4) {
                float s = __ldg(&b_out[tid]);
                #pragma unroll
                for (int w = 0; w < 8; w++) s += red[tid*8 + w];
                dout[(b*DECL + t)*TT + tid] = s;
                red[32 + tid] = s;
            }
            __syncthreads();
            if (tid < FF)
                __stcg(&g_cur[b*FF + tid], __ldg(&inputs[(b*DECL + t)*FF + tid]));
            __syncthreads();
            if (tid < TT)
                __stcg(&g_cur[b*FF + __ldg(&tind[tid])], red[32 + tid]);
        }
        if (t < DECL - 1) gsync();
    }
}

// ---------------- launch ----------------
extern "C" void kernel_launch(void* const* d_in, const int* in_sizes, int n_in,
                              void* d_out, int out_size)
{
    const float* inputs   = (const float*)d_in[0];
    const float* hidden   = (const float*)d_in[1];
    const float* enc      = (const float*)d_in[2];
    const int*   tindices = (const int*)  d_in[3];
    const float* W_attn   = (const float*)d_in[4];
    const float* b_attn   = (const float*)d_in[5];
    const float* v_attn   = (const float*)d_in[6];
    const float* Wi0      = (const float*)d_in[7];
    const float* Wh0      = (const float*)d_in[8];
    const float* bi0      = (const float*)d_in[9];
    const float* bh0      = (const float*)d_in[10];
    const float* Wi1      = (const float*)d_in[11];
    const float* Wh1      = (const float*)d_in[12];
    const float* bi1      = (const float*)d_in[13];
    const float* bh1      = (const float*)d_in[14];
    const float* W_out    = (const float*)d_in[15];
    const float* b_out    = (const float*)d_in[16];
    float* out = (float*)d_out;

    k_decoder<<<NBLK, 256>>>(inputs, hidden, enc, tindices,
                             W_attn, b_attn, v_attn,
                             Wi0, Wh0, bi0, bh0,
                             Wi1, Wh1, bi1, bh1,
                             W_out, b_out, out);
}

// round 13
// speedup vs baseline: 1.1406x; 1.1406x over previous
#include <cuda_runtime.h>
#include <cuda_bf16.h>
#include <math.h>

typedef unsigned int uint;
typedef __nv_bfloat16 bf16;

#define BB   64
#define DECL 12
#define FF   32
#define HH   512
#define EE   96
#define TT   4
#define G3   1536
#define NPRE 3584   /* 512 (query) + 1536 (gh0) + 1536 (gh1) */
#define KX0  544    /* F + H */
#define KOUT 1056   /* 2H + F */
#define NBLK 148
#define SRB  72     /* bf16 smem plane row stride */
#define PLANE (64*SRB)          /* 4608 elems = 9216 B */
#define SMEM_DYN (8*PLANE*2 + 1100*4)   /* 73728 + 4400 = 78128 B */

// ---------------- fp32 scratch ----------------
__device__ __align__(16) float g_encproj[BB*EE*HH];
__device__ __align__(16) float g_h0[BB*HH];
__device__ __align__(16) float g_h1[BB*HH];
__device__ __align__(16) float g_cur[BB*FF];
__device__ __align__(16) float g_pre[2][BB*NPRE];     // K-split x2: query|gh0|gh1
__device__ __align__(16) float g_gi[4][BB*G3];        // K-split x4 for gi
__device__ __align__(16) float g_ws[BB*HH];
__device__ __align__(16) float g_sc[BB*EE];

// ---------------- bf16 hi/lo planes ----------------
__device__ __align__(16) bf16 gb_encH[BB*EE*HH], gb_encL[BB*EE*HH];
__device__ __align__(16) bf16 gb_WaeH[HH*HH],    gb_WaeL[HH*HH];
__device__ __align__(16) bf16 gb_WahH[HH*HH],    gb_WahL[HH*HH];
__device__ __align__(16) bf16 gb_Wh0H[G3*HH],    gb_Wh0L[G3*HH];
__device__ __align__(16) bf16 gb_Wh1H[G3*HH],    gb_Wh1L[G3*HH];
__device__ __align__(16) bf16 gb_Wi0H[G3*KX0],   gb_Wi0L[G3*KX0];
__device__ __align__(16) bf16 gb_Wi1H[G3*HH],    gb_Wi1L[G3*HH];
__device__ __align__(16) bf16 gb_h0H[BB*HH],     gb_h0L[BB*HH];
__device__ __align__(16) bf16 gb_h1H[BB*HH],     gb_h1L[BB*HH];
__device__ __align__(16) bf16 gb_x0H[BB*KX0],    gb_x0L[BB*KX0];

__device__ unsigned g_bar_cnt = 0;
__device__ unsigned g_bar_gen = 0;

// ---------------- helpers ----------------
__device__ __forceinline__ float fast_sigmoid(float x) {
    return 1.0f / (1.0f + __expf(-x));
}
__device__ __forceinline__ float fast_tanh(float x) {
    float e = __expf(-2.0f * fabsf(x));
    float t = (1.0f - e) / (1.0f + e);
    return copysignf(t, x);
}
__device__ __forceinline__ void split1(float x, bf16 &h, bf16 &l) {
    h = __float2bfloat16(x);
    l = __float2bfloat16(x - __bfloat162float(h));
}
__device__ __forceinline__ uint lds32b(const bf16* p, int r, int c) {
    return *reinterpret_cast<const uint*>(&p[r*SRB + c]);
}
__device__ __forceinline__ void mma16816(float* d, const uint* a, uint b0, uint b1) {
    asm volatile(
        "mma.sync.aligned.m16n8k16.row.col.f32.bf16.bf16.f32 "
        "{%0,%1,%2,%3},{%4,%5,%6,%7},{%8,%9},{%0,%1,%2,%3};"
        : "+f"(d[0]), "+f"(d[1]), "+f"(d[2]), "+f"(d[3])
        : "r"(a[0]), "r"(a[1]), "r"(a[2]), "r"(a[3]), "r"(b0), "r"(b1));
}
__device__ __forceinline__ void cpa16(bf16* dst, const bf16* src) {
    uint d = (uint)__cvta_generic_to_shared(dst);
    asm volatile("cp.async.cg.shared.global [%0], [%1], 16;" :: "r"(d), "l"(src) : "memory");
}

// grid barrier
__device__ __forceinline__ void gsync() {
    __syncthreads();
    if (threadIdx.x == 0) {
        __threadfence();
        unsigned gen = *((volatile unsigned*)&g_bar_gen);
        if (atomicAdd(&g_bar_cnt, 1u) == (unsigned)(NBLK - 1)) {
            g_bar_cnt = 0;
            __threadfence();
            *((volatile unsigned*)&g_bar_gen) = gen + 1u;
        } else {
            while (*((volatile unsigned*)&g_bar_gen) == gen) { }
        }
    }
    __syncthreads();
}

// ---------------- cp.async double-buffered bf16x3 TC GEMM ----------------
// C[64][64] = A[64][klen] @ W[64][klen]^T ; klen % 32 == 0; 512 threads.
__device__ __forceinline__ void gemm_job(
    bf16* __restrict__ sPl,
    const bf16* __restrict__ AH, const bf16* __restrict__ AL, int lda,
    const bf16* __restrict__ WH, const bf16* __restrict__ WL, int ldw,
    float* __restrict__ C, int ldc, int klen)
{
    const int tid  = threadIdx.x;
    const int warp = tid >> 5, lane = tid & 31;
    const int rt = warp >> 2, ct = warp & 3;       // warp tile 16x16
    const int g  = lane >> 2;
    const int q  = (lane & 3) << 1;
    const int srow = tid >> 3, sc8 = (tid & 7) << 3;
    float d[2][4] = {};
    const int nch = (klen + 63) >> 6;

    // prologue: issue chunk 0 into buf 0
    {
        if (sc8 < klen) {
            cpa16(&sPl[0*PLANE + srow*SRB + sc8], &AH[srow*lda + sc8]);
            cpa16(&sPl[1*PLANE + srow*SRB + sc8], &AL[srow*lda + sc8]);
            cpa16(&sPl[2*PLANE + srow*SRB + sc8], &WH[srow*ldw + sc8]);
            cpa16(&sPl[3*PLANE + srow*SRB + sc8], &WL[srow*ldw + sc8]);
        }
        asm volatile("cp.async.commit_group;" ::: "memory");
    }

    for (int c = 0; c < nch; c++) {
        const int buf = c & 1;
        if (c + 1 < nch) {
            const int k1 = (c + 1) << 6;
            const int rem1 = klen - k1;
            bf16* b1 = sPl + (buf ^ 1)*4*PLANE;
            if (sc8 < rem1) {
                const int off = k1 + sc8;
                cpa16(&b1[0*PLANE + srow*SRB + sc8], &AH[srow*lda + off]);
                cpa16(&b1[1*PLANE + srow*SRB + sc8], &AL[srow*lda + off]);
                cpa16(&b1[2*PLANE + srow*SRB + sc8], &WH[srow*ldw + off]);
                cpa16(&b1[3*PLANE + srow*SRB + sc8], &WL[srow*ldw + off]);
            }
            asm volatile("cp.async.commit_group;" ::: "memory");
            asm volatile("cp.async.wait_group 1;" ::: "memory");
        } else {
            asm volatile("cp.async.wait_group 0;" ::: "memory");
        }
        __syncthreads();

        const bf16* sAH = sPl + buf*4*PLANE;
        const bf16* sAL = sAH + PLANE;
        const bf16* sWH = sAH + 2*PLANE;
        const bf16* sWL = sAH + 3*PLANE;
        const int rem = klen - (c << 6);
        #pragma unroll
        for (int ks = 0; ks < 64; ks += 16) {
            if (ks < rem) {
                uint aH[4], aL[4];
                const int r0 = rt*16 + g;
                aH[0] = lds32b(sAH, r0,     ks+q);   aH[1] = lds32b(sAH, r0 + 8, ks+q);
                aH[2] = lds32b(sAH, r0,     ks+q+8); aH[3] = lds32b(sAH, r0 + 8, ks+q+8);
                aL[0] = lds32b(sAL, r0,     ks+q);   aL[1] = lds32b(sAL, r0 + 8, ks+q);
                aL[2] = lds32b(sAL, r0,     ks+q+8); aL[3] = lds32b(sAL, r0 + 8, ks+q+8);
                #pragma unroll
                for (int nt = 0; nt < 2; nt++) {
                    const int n0 = ct*16 + nt*8 + g;
                    uint bH0 = lds32b(sWH, n0, ks+q), bH1 = lds32b(sWH, n0, ks+q+8);
                    uint bL0 = lds32b(sWL, n0, ks+q), bL1 = lds32b(sWL, n0, ks+q+8);
                    mma16816(d[nt], aH, bH0, bH1);
                    mma16816(d[nt], aH, bL0, bL1);
                    mma16816(d[nt], aL, bH0, bH1);
                }
            }
        }
        __syncthreads();
    }

    const int r0 = rt*16 + g;
    #pragma unroll
    for (int nt = 0; nt < 2; nt++) {
        const int c0 = ct*16 + nt*8 + q;
        __stcg(reinterpret_cast<float2*>(&C[r0*ldc + c0]),       make_float2(d[nt][0], d[nt][1]));
        __stcg(reinterpret_cast<float2*>(&C[(r0 + 8)*ldc + c0]), make_float2(d[nt][2], d[nt][3]));
    }
}

// ---------------- the whole decoder, persistent ----------------
__global__ __launch_bounds__(512, 1) void k_decoder(
    const float* __restrict__ inputs, const float* __restrict__ hidden,
    const float* __restrict__ enc,    const int* __restrict__ tind,
    const float* __restrict__ Wattn,  const float* __restrict__ b_attn,
    const float* __restrict__ v_attn,
    const float* __restrict__ Wi0, const float* __restrict__ Wh0,
    const float* __restrict__ bi0, const float* __restrict__ bh0,
    const float* __restrict__ Wi1, const float* __restrict__ Wh1,
    const float* __restrict__ bi1, const float* __restrict__ bh1,
    const float* __restrict__ W_out, const float* __restrict__ b_out,
    float* __restrict__ dout)
{
    extern __shared__ __align__(16) char smem_raw[];
    bf16*  sPl  = reinterpret_cast<bf16*>(smem_raw);
    float* sBuf = reinterpret_cast<float*>(smem_raw + 8*PLANE*2);

    const int bid  = blockIdx.x;
    const int tid  = threadIdx.x;
    const int warp = tid >> 5, lane = tid & 31;   // 16 warps
    const int gtid = bid*512 + tid;
    const int gstr = NBLK*512;

    // ===== init: copies + one-time bf16 splits =====
    for (int i = gtid; i < BB*HH; i += gstr) {
        float h0v = __ldg(&hidden[i]);
        float h1v = __ldg(&hidden[BB*HH + i]);
        __stcg(&g_h0[i], h0v);
        __stcg(&g_h1[i], h1v);
        bf16 hh, hl;
        split1(h0v, hh, hl); __stcg(&gb_h0H[i], hh); __stcg(&gb_h0L[i], hl);
        split1(h1v, hh, hl); __stcg(&gb_h1H[i], hh); __stcg(&gb_h1L[i], hl);
    }
    for (int i = gtid; i < BB*FF; i += gstr) {
        int b = i >> 5, f = i & 31;
        __stcg(&g_cur[i], __ldg(&inputs[b*DECL*FF + f]));
    }
    for (int i = gtid; i < BB*EE*HH; i += gstr) {
        bf16 h, l; split1(__ldg(&enc[i]), h, l);
        __stcg(&gb_encH[i], h); __stcg(&gb_encL[i], l);
    }
    for (int i = gtid; i < HH*HH; i += gstr) {
        int gg = i >> 9, k = i & 511;
        bf16 h, l;
        split1(__ldg(&Wattn[gg*(2*HH) + k]), h, l);
        __stcg(&gb_WahH[i], h); __stcg(&gb_WahL[i], l);
        split1(__ldg(&Wattn[gg*(2*HH) + HH + k]), h, l);
        __stcg(&gb_WaeH[i], h); __stcg(&gb_WaeL[i], l);
    }
    for (int i = gtid; i < G3*HH; i += gstr) {
        bf16 h, l;
        split1(__ldg(&Wh0[i]), h, l); __stcg(&gb_Wh0H[i], h); __stcg(&gb_Wh0L[i], l);
        split1(__ldg(&Wh1[i]), h, l); __stcg(&gb_Wh1H[i], h); __stcg(&gb_Wh1L[i], l);
        split1(__ldg(&Wi1[i]), h, l); __stcg(&gb_Wi1H[i], h); __stcg(&gb_Wi1L[i], l);
    }
    for (int i = gtid; i < G3*KX0; i += gstr) {
        bf16 h, l; split1(__ldg(&Wi0[i]), h, l);
        __stcg(&gb_Wi0H[i], h); __stcg(&gb_Wi0L[i], l);
    }
    gsync();

    // ===== phase E: enc_proj (96 M-tiles x 8 N-tiles, K=512) =====
    for (int it = bid; it < 96*8; it += NBLK) {
        int m = it >> 3, n = it & 7;
        gemm_job(sPl,
                 gb_encH + m*64*HH, gb_encL + m*64*HH, HH,
                 gb_WaeH + n*64*HH, gb_WaeL + n*64*HH, HH,
                 g_encproj + m*64*HH + n*64, HH, HH);
    }
    gsync();

    // ===== 12 decode steps =====
    for (int t = 0; t < DECL; t++) {
        // --- PA: query (8Nx2K=16 jobs) + gh0/gh1 (48Nx2K=96 jobs) = 112 jobs, K=256
        for (int it = bid; it < 112; it += NBLK) {
            int col0, s;
            const bf16 *AH, *AL, *WH, *WL;
            if (it < 16) {
                col0 = (it >> 1) * 64; s = it & 1;
                AH = gb_h1H; AL = gb_h1L;
                WH = gb_WahH + col0*HH; WL = gb_WahL + col0*HH;
            } else {
                int jt = it - 16;
                col0 = 512 + (jt >> 1) * 64; s = jt & 1;
                if (col0 < 2048) {
                    AH = gb_h0H; AL = gb_h0L;
                    WH = gb_Wh0H + (col0-512)*HH; WL = gb_Wh0L + (col0-512)*HH;
                } else {
                    AH = gb_h1H; AL = gb_h1L;
                    WH = gb_Wh1H + (col0-2048)*HH; WL = gb_Wh1L + (col0-2048)*HH;
                }
            }
            int k0 = s * 256;
            gemm_job(sPl, AH + k0, AL + k0, HH, WH + k0, WL + k0, HH,
                     g_pre[s] + col0, NPRE, 256);
        }
        gsync();

        // --- PB: scores: job = (b, part6), 16 energies (one per warp); 384 jobs
        for (int it = bid; it < BB*6; it += NBLK) {
            __syncthreads();
            int b = it / 6, part = it % 6;
            float* qs = sBuf;
            float* vs = sBuf + 512;
            float qv = __ldg(&b_attn[tid])
                     + __ldcg(&g_pre[0][b*NPRE + tid])
                     + __ldcg(&g_pre[1][b*NPRE + tid]);
            qs[tid] = qv;
            vs[tid] = __ldg(&v_attn[tid]);
            __syncthreads();
            int e = part*16 + warp;
            const float4* ep4 = reinterpret_cast<const float4*>(g_encproj + (b*EE + e)*HH);
            float ssum = 0.0f;
            #pragma unroll
            for (int i = 0; i < 4; i++) {
                float4 v = __ldcg(&ep4[i*32 + lane]);
                int gg = (i*32 + lane) * 4;
                ssum += fast_tanh(v.x + qs[gg  ]) * vs[gg  ];
                ssum += fast_tanh(v.y + qs[gg+1]) * vs[gg+1];
                ssum += fast_tanh(v.z + qs[gg+2]) * vs[gg+2];
                ssum += fast_tanh(v.w + qs[gg+3]) * vs[gg+3];
            }
            #pragma unroll
            for (int off = 16; off > 0; off >>= 1)
                ssum += __shfl_xor_sync(0xffffffffu, ssum, off);
            if (lane == 0) __stcg(&g_sc[b*EE + e], ssum);
        }
        gsync();

        // --- PC: softmax + ws + assemble x0 : 64 jobs
        for (int it = bid; it < BB; it += NBLK) {
            __syncthreads();
            int b = it;
            float* sc = sBuf;
            if (warp == 0) {
                float s0 = __ldcg(&g_sc[b*EE + lane]);
                float s1 = __ldcg(&g_sc[b*EE + lane + 32]);
                float s2 = __ldcg(&g_sc[b*EE + lane + 64]);
                float m = fmaxf(s0, fmaxf(s1, s2));
                #pragma unroll
                for (int off = 16; off > 0; off >>= 1)
                    m = fmaxf(m, __shfl_xor_sync(0xffffffffu, m, off));
                float p0 = __expf(s0-m), p1 = __expf(s1-m), p2 = __expf(s2-m);
                float sum = p0 + p1 + p2;
                #pragma unroll
                for (int off = 16; off > 0; off >>= 1)
                    sum += __shfl_xor_sync(0xffffffffu, sum, off);
                float inv = 1.0f / sum;
                sc[lane] = p0*inv; sc[lane+32] = p1*inv; sc[lane+64] = p2*inv;
            }
            __syncthreads();
            float acc = 0.0f;
            const float* eb = enc + b*EE*HH + tid;
            #pragma unroll 8
            for (int e = 0; e < EE; e++) acc += sc[e] * __ldg(&eb[e*HH]);
            __stcg(&g_ws[b*HH + tid], acc);
            bf16 h, l; split1(acc, h, l);
            __stcg(&gb_x0H[b*KX0 + FF + tid], h);
            __stcg(&gb_x0L[b*KX0 + FF + tid], l);
            if (tid < FF) {
                float cv = __ldcg(&g_cur[b*FF + tid]);
                split1(cv, h, l);
                __stcg(&gb_x0H[b*KX0 + tid], h);
                __stcg(&gb_x0L[b*KX0 + tid], l);
            }
        }
        gsync();

        // --- PD: gi0 = x0 @ Wi0^T : 24 N-tiles x Ksplit4 {128,128,128,160} = 96 jobs
        for (int it = bid; it < 96; it += NBLK) {
            int col0 = (it >> 2) * 64;
            int s    = it & 3;
            int k0   = s * 128;
            int klen = (s == 3) ? 160 : 128;
            gemm_job(sPl, gb_x0H + k0, gb_x0L + k0, KX0,
                     gb_Wi0H + col0*KX0 + k0, gb_Wi0L + col0*KX0 + k0, KX0,
                     g_gi[s] + col0, G3, klen);
        }
        gsync();

        // --- PE: GRU combine layer 0 -> h0 : 64 jobs
        for (int it = bid; it < BB; it += NBLK) {
            int b = it, j = tid;
            float ir = __ldg(&bi0[j]), iz = __ldg(&bi0[j+HH]), in_ = __ldg(&bi0[j+2*HH]);
            float hr = __ldg(&bh0[j]), hz = __ldg(&bh0[j+HH]), hn  = __ldg(&bh0[j+2*HH]);
            #pragma unroll
            for (int s = 0; s < 4; s++) {
                const float* gi = g_gi[s] + b*G3;
                ir += __ldcg(&gi[j]); iz += __ldcg(&gi[j+HH]); in_ += __ldcg(&gi[j+2*HH]);
            }
            #pragma unroll
            for (int s = 0; s < 2; s++) {
                const float* gh = g_pre[s] + b*NPRE + 512;
                hr += __ldcg(&gh[j]); hz += __ldcg(&gh[j+HH]); hn += __ldcg(&gh[j+2*HH]);
            }
            float r = fast_sigmoid(ir + hr);
            float z = fast_sigmoid(iz + hz);
            float n = fast_tanh(in_ + r * hn);
            float hp = __ldcg(&g_h0[b*HH + j]);
            float h0n = (1.0f - z)*n + z*hp;
            __stcg(&g_h0[b*HH + j], h0n);
            bf16 h, l; split1(h0n, h, l);
            __stcg(&gb_h0H[b*HH + j], h);
            __stcg(&gb_h0L[b*HH + j], l);
        }
        gsync();

        // --- PF: gi1 = h0_new @ Wi1^T : 24 N-tiles x Ksplit4(128) = 96 jobs
        for (int it = bid; it < 96; it += NBLK) {
            int col0 = (it >> 2) * 64;
            int s    = it & 3;
            int k0   = s * 128;
            gemm_job(sPl, gb_h0H + k0, gb_h0L + k0, HH,
                     gb_Wi1H + col0*HH + k0, gb_Wi1L + col0*HH + k0, HH,
                     g_gi[s] + col0, G3, 128);
        }
        gsync();

        // --- PG: GRU combine layer 1 -> h1, fused out-proj + next cur : 64 jobs
        for (int it = bid; it < BB; it += NBLK) {
            __syncthreads();
            int b = it, j = tid;
            float* ho  = sBuf;          // 512
            float* red = sBuf + 512;    // 64 + 4
            float ir = __ldg(&bi1[j]), iz = __ldg(&bi1[j+HH]), in_ = __ldg(&bi1[j+2*HH]);
            float hr = __ldg(&bh1[j]), hz = __ldg(&bh1[j+HH]), hn  = __ldg(&bh1[j+2*HH]);
            #pragma unroll
            for (int s = 0; s < 4; s++) {
                const float* gi = g_gi[s] + b*G3;
                ir += __ldcg(&gi[j]); iz += __ldcg(&gi[j+HH]); in_ += __ldcg(&gi[j+2*HH]);
            }
            #pragma unroll
            for (int s = 0; s < 2; s++) {
                const float* gh = g_pre[s] + b*NPRE + 2048;
                hr += __ldcg(&gh[j]); hz += __ldcg(&gh[j+HH]); hn += __ldcg(&gh[j+2*HH]);
            }
            float r = fast_sigmoid(ir + hr);
            float z = fast_sigmoid(iz + hz);
            float n = fast_tanh(in_ + r * hn);
            float hp = __ldcg(&g_h1[b*HH + j]);
            float h1n = (1.0f - z)*n + z*hp;
            __stcg(&g_h1[b*HH + j], h1n);
            bf16 h, l; split1(h1n, h, l);
            __stcg(&gb_h1H[b*HH + j], h);
            __stcg(&gb_h1L[b*HH + j], l);
            ho[j] = h1n;
            __syncthreads();

            float a0 = 0.f, a1 = 0.f, a2 = 0.f, a3 = 0.f;
            for (int k = tid; k < KOUT; k += 512) {
                float x;
                if (k < HH)          x = ho[k];
                else if (k < 2*HH)   x = __ldcg(&g_ws[b*HH + k - HH]);
                else                 x = __ldcg(&g_cur[b*FF + (k - 2*HH)]);
                a0 += x * __ldg(&W_out[k]);
                a1 += x * __ldg(&W_out[KOUT + k]);
                a2 += x * __ldg(&W_out[2*KOUT + k]);
                a3 += x * __ldg(&W_out[3*KOUT + k]);
            }
            #pragma unroll
            for (int off = 16; off > 0; off >>= 1) {
                a0 += __shfl_xor_sync(0xffffffffu, a0, off);
                a1 += __shfl_xor_sync(0xffffffffu, a1, off);
                a2 += __shfl_xor_sync(0xffffffffu, a2, off);
                a3 += __shfl_xor_sync(0xffffffffu, a3, off);
            }
            if (lane == 0) {
                red[0*16 + warp] = a0; red[1*16 + warp] = a1;
                red[2*16 + warp] = a2; red[3*16 + warp] = a3;
            }
            __syncthreads();
            if (tid < 4) {
                float s = __ldg(&b_out[tid]);
                #pragma unroll
                for (int w = 0; w < 16; w++) s += red[tid*16 + w];
                dout[(b*DECL + t)*TT + tid] = s;
                red[64 + tid] = s;
            }
            __syncthreads();
            if (tid < FF)
                __stcg(&g_cur[b*FF + tid], __ldg(&inputs[(b*DECL + t)*FF + tid]));
            __syncthreads();
            if (tid < TT)
                __stcg(&g_cur[b*FF + __ldg(&tind[tid])], red[64 + tid]);
        }
        if (t < DECL - 1) gsync();
    }
}

// ---------------- launch ----------------
extern "C" void kernel_launch(void* const* d_in, const int* in_sizes, int n_in,
                              void* d_out, int out_size)
{
    const float* inputs   = (const float*)d_in[0];
    const float* hidden   = (const float*)d_in[1];
    const float* enc      = (const float*)d_in[2];
    const int*   tindices = (const int*)  d_in[3];
    const float* W_attn   = (const float*)d_in[4];
    const float* b_attn   = (const float*)d_in[5];
    const float* v_attn   = (const float*)d_in[6];
    const float* Wi0      = (const float*)d_in[7];
    const float* Wh0      = (const float*)d_in[8];
    const float* bi0      = (const float*)d_in[9];
    const float* bh0      = (const float*)d_in[10];
    const float* Wi1      = (const float*)d_in[11];
    const float* Wh1      = (const float*)d_in[12];
    const float* bi1      = (const float*)d_in[13];
    const float* bh1      = (const float*)d_in[14];
    const float* W_out    = (const float*)d_in[15];
    const float* b_out    = (const float*)d_in[16];
    float* out = (float*)d_out;

    static bool attr_set = false;
    if (!attr_set) {
        cudaFuncSetAttribute(k_decoder, cudaFuncAttributeMaxDynamicSharedMemorySize, SMEM_DYN);
        attr_set = true;
    }
    k_decoder<<<NBLK, 512, SMEM_DYN>>>(inputs, hidden, enc, tindices,
                                       W_attn, b_attn, v_attn,
                                       Wi0, Wh0, bi0, bh0,
                                       Wi1, Wh1, bi1, bh1,
                                       W_out, b_out, out);
}

// round 14
// speedup vs baseline: 1.1637x; 1.0202x over previous
#include <cuda_runtime.h>
#include <cuda_bf16.h>
#include <math.h>

typedef unsigned int uint;
typedef __nv_bfloat16 bf16;

#define BB   64
#define DECL 12
#define FF   32
#define HH   512
#define EE   96
#define TT   4
#define G3   1536
#define NPRE 3584   /* 512 (query) + 1536 (gh0) + 1536 (gh1) */
#define KX0  544    /* F + H */
#define KOUT 1056   /* 2H + F */
#define NBLK 148
#define SRB  72     /* bf16 smem plane row stride */
#define PLANE (64*SRB)          /* 4608 elems = 9216 B */
#define SMEM_DYN (8*PLANE*2 + 1100*4)   /* 73728 + 4400 = 78128 B */

// ---------------- fp32 scratch ----------------
__device__ __align__(16) float g_encproj[BB*EE*HH];
__device__ __align__(16) float g_h0[BB*HH];
__device__ __align__(16) float g_h1[BB*HH];
__device__ __align__(16) float g_cur[BB*FF];
__device__ __align__(16) float g_pre[2][BB*NPRE];     // K-split x2: query|gh0|gh1
__device__ __align__(16) float g_gi[4][BB*G3];        // K-split x4 for gi
__device__ __align__(16) float g_ws[BB*HH];
__device__ __align__(16) float g_sc[BB*EE];

// ---------------- bf16 hi/lo planes ----------------
__device__ __align__(16) bf16 gb_encH[BB*EE*HH], gb_encL[BB*EE*HH];
__device__ __align__(16) bf16 gb_WaeH[HH*HH],    gb_WaeL[HH*HH];
__device__ __align__(16) bf16 gb_WahH[HH*HH],    gb_WahL[HH*HH];
__device__ __align__(16) bf16 gb_Wh0H[G3*HH],    gb_Wh0L[G3*HH];
__device__ __align__(16) bf16 gb_Wh1H[G3*HH],    gb_Wh1L[G3*HH];
__device__ __align__(16) bf16 gb_Wi0H[G3*KX0],   gb_Wi0L[G3*KX0];
__device__ __align__(16) bf16 gb_Wi1H[G3*HH],    gb_Wi1L[G3*HH];
__device__ __align__(16) bf16 gb_h0H[BB*HH],     gb_h0L[BB*HH];
__device__ __align__(16) bf16 gb_h1H[BB*HH],     gb_h1L[BB*HH];
__device__ __align__(16) bf16 gb_x0H[BB*KX0],    gb_x0L[BB*KX0];

__device__ unsigned g_bar_cnt = 0;
__device__ unsigned g_bar_gen = 0;

// ---------------- helpers ----------------
__device__ __forceinline__ float fast_sigmoid(float x) {
    return 1.0f / (1.0f + __expf(-x));
}
__device__ __forceinline__ float fast_tanh(float x) {
    float e = __expf(-2.0f * fabsf(x));
    float t = (1.0f - e) / (1.0f + e);
    return copysignf(t, x);
}
__device__ __forceinline__ void split1(float x, bf16 &h, bf16 &l) {
    h = __float2bfloat16(x);
    l = __float2bfloat16(x - __bfloat162float(h));
}
__device__ __forceinline__ void mma16816(float* d, const uint* a, uint b0, uint b1) {
    asm volatile(
        "mma.sync.aligned.m16n8k16.row.col.f32.bf16.bf16.f32 "
        "{%0,%1,%2,%3},{%4,%5,%6,%7},{%8,%9},{%0,%1,%2,%3};"
        : "+f"(d[0]), "+f"(d[1]), "+f"(d[2]), "+f"(d[3])
        : "r"(a[0]), "r"(a[1]), "r"(a[2]), "r"(a[3]), "r"(b0), "r"(b1));
}
__device__ __forceinline__ void ldsm4(uint* r, uint addr) {
    asm volatile("ldmatrix.sync.aligned.m8n8.x4.shared.b16 {%0,%1,%2,%3}, [%4];"
                 : "=r"(r[0]), "=r"(r[1]), "=r"(r[2]), "=r"(r[3]) : "r"(addr));
}
__device__ __forceinline__ void cpa16(bf16* dst, const bf16* src) {
    uint d = (uint)__cvta_generic_to_shared(dst);
    asm volatile("cp.async.cg.shared.global [%0], [%1], 16;" :: "r"(d), "l"(src) : "memory");
}

// grid barrier
__device__ __forceinline__ void gsync() {
    __syncthreads();
    if (threadIdx.x == 0) {
        __threadfence();
        unsigned gen = *((volatile unsigned*)&g_bar_gen);
        if (atomicAdd(&g_bar_cnt, 1u) == (unsigned)(NBLK - 1)) {
            g_bar_cnt = 0;
            __threadfence();
            *((volatile unsigned*)&g_bar_gen) = gen + 1u;
        } else {
            while (*((volatile unsigned*)&g_bar_gen) == gen) { }
        }
    }
    __syncthreads();
}

// ---------------- cp.async double-buffered bf16x3 TC GEMM (ldmatrix) ----------------
// C[64][64] = A[64][klen] @ W[64][klen]^T ; klen % 32 == 0; 512 threads.
__device__ __forceinline__ void gemm_job(
    bf16* __restrict__ sPl,
    const bf16* __restrict__ AH, const bf16* __restrict__ AL, int lda,
    const bf16* __restrict__ WH, const bf16* __restrict__ WL, int ldw,
    float* __restrict__ C, int ldc, int klen)
{
    const int tid  = threadIdx.x;
    const int warp = tid >> 5, lane = tid & 31;
    const int rt = warp >> 2, ct = warp & 3;       // warp tile 16x16
    const int q  = (lane & 3) << 1;
    const int srow = tid >> 3, sc8 = (tid & 7) << 3;
    // ldmatrix lane->address mapping (byte offsets within a plane)
    //   A fragment: regs [r-lo/k-lo, r-hi/k-lo, r-lo/k-hi, r-hi/k-hi]
    const int a_off = ((rt*16 + (((lane>>3)&1)<<3) + (lane&7)) * SRB
                       + ((lane>>4)<<3)) * 2;
    //   B fragment: regs [b0(nt0), b1(nt0), b0(nt1), b1(nt1)]
    const int b_off = ((ct*16 + ((lane>>4)<<3) + (lane&7)) * SRB
                       + (((lane>>3)&1)<<3)) * 2;
    float d[2][4] = {};
    const int nch = (klen + 63) >> 6;

    // prologue: issue chunk 0 into buf 0
    {
        if (sc8 < klen) {
            cpa16(&sPl[0*PLANE + srow*SRB + sc8], &AH[srow*lda + sc8]);
            cpa16(&sPl[1*PLANE + srow*SRB + sc8], &AL[srow*lda + sc8]);
            cpa16(&sPl[2*PLANE + srow*SRB + sc8], &WH[srow*ldw + sc8]);
            cpa16(&sPl[3*PLANE + srow*SRB + sc8], &WL[srow*ldw + sc8]);
        }
        asm volatile("cp.async.commit_group;" ::: "memory");
    }

    for (int c = 0; c < nch; c++) {
        const int buf = c & 1;
        if (c + 1 < nch) {
            const int k1 = (c + 1) << 6;
            const int rem1 = klen - k1;
            bf16* b1 = sPl + (buf ^ 1)*4*PLANE;
            if (sc8 < rem1) {
                const int off = k1 + sc8;
                cpa16(&b1[0*PLANE + srow*SRB + sc8], &AH[srow*lda + off]);
                cpa16(&b1[1*PLANE + srow*SRB + sc8], &AL[srow*lda + off]);
                cpa16(&b1[2*PLANE + srow*SRB + sc8], &WH[srow*ldw + off]);
                cpa16(&b1[3*PLANE + srow*SRB + sc8], &WL[srow*ldw + off]);
            }
            asm volatile("cp.async.commit_group;" ::: "memory");
            asm volatile("cp.async.wait_group 1;" ::: "memory");
        } else {
            asm volatile("cp.async.wait_group 0;" ::: "memory");
        }
        __syncthreads();

        const bf16* base = sPl + buf*4*PLANE;
        const uint sbase = (uint)__cvta_generic_to_shared(base);
        const uint aAH = sbase + a_off;
        const uint aAL = aAH + PLANE*2;
        const uint aWH = sbase + 2*PLANE*2 + b_off;
        const uint aWL = aWH + PLANE*2;
        const int rem = klen - (c << 6);
        #pragma unroll
        for (int ks = 0; ks < 64; ks += 16) {
            if (ks < rem) {
                uint aH[4], aL[4], bh[4], bl[4];
                ldsm4(aH, aAH + ks*2);
                ldsm4(aL, aAL + ks*2);
                ldsm4(bh, aWH + ks*2);
                ldsm4(bl, aWL + ks*2);
                mma16816(d[0], aH, bh[0], bh[1]);
                mma16816(d[1], aH, bh[2], bh[3]);
                mma16816(d[0], aH, bl[0], bl[1]);
                mma16816(d[1], aH, bl[2], bl[3]);
                mma16816(d[0], aL, bh[0], bh[1]);
                mma16816(d[1], aL, bh[2], bh[3]);
            }
        }
        __syncthreads();
    }

    const int g = lane >> 2;
    const int r0 = rt*16 + g;
    #pragma unroll
    for (int nt = 0; nt < 2; nt++) {
        const int c0 = ct*16 + nt*8 + q;
        __stcg(reinterpret_cast<float2*>(&C[r0*ldc + c0]),       make_float2(d[nt][0], d[nt][1]));
        __stcg(reinterpret_cast<float2*>(&C[(r0 + 8)*ldc + c0]), make_float2(d[nt][2], d[nt][3]));
    }
}

// ---------------- the whole decoder, persistent ----------------
__global__ __launch_bounds__(512, 1) void k_decoder(
    const float* __restrict__ inputs, const float* __restrict__ hidden,
    const float* __restrict__ enc,    const int* __restrict__ tind,
    const float* __restrict__ Wattn,  const float* __restrict__ b_attn,
    const float* __restrict__ v_attn,
    const float* __restrict__ Wi0, const float* __restrict__ Wh0,
    const float* __restrict__ bi0, const float* __restrict__ bh0,
    const float* __restrict__ Wi1, const float* __restrict__ Wh1,
    const float* __restrict__ bi1, const float* __restrict__ bh1,
    const float* __restrict__ W_out, const float* __restrict__ b_out,
    float* __restrict__ dout)
{
    extern __shared__ __align__(16) char smem_raw[];
    bf16*  sPl  = reinterpret_cast<bf16*>(smem_raw);
    float* sBuf = reinterpret_cast<float*>(smem_raw + 8*PLANE*2);

    const int bid  = blockIdx.x;
    const int tid  = threadIdx.x;
    const int warp = tid >> 5, lane = tid & 31;   // 16 warps
    const int gtid = bid*512 + tid;
    const int gstr = NBLK*512;

    // ===== init: copies + one-time bf16 splits =====
    for (int i = gtid; i < BB*HH; i += gstr) {
        float h0v = __ldg(&hidden[i]);
        float h1v = __ldg(&hidden[BB*HH + i]);
        __stcg(&g_h0[i], h0v);
        __stcg(&g_h1[i], h1v);
        bf16 hh, hl;
        split1(h0v, hh, hl); __stcg(&gb_h0H[i], hh); __stcg(&gb_h0L[i], hl);
        split1(h1v, hh, hl); __stcg(&gb_h1H[i], hh); __stcg(&gb_h1L[i], hl);
    }
    for (int i = gtid; i < BB*FF; i += gstr) {
        int b = i >> 5, f = i & 31;
        __stcg(&g_cur[i], __ldg(&inputs[b*DECL*FF + f]));
    }
    for (int i = gtid; i < BB*EE*HH; i += gstr) {
        bf16 h, l; split1(__ldg(&enc[i]), h, l);
        __stcg(&gb_encH[i], h); __stcg(&gb_encL[i], l);
    }
    for (int i = gtid; i < HH*HH; i += gstr) {
        int gg = i >> 9, k = i & 511;
        bf16 h, l;
        split1(__ldg(&Wattn[gg*(2*HH) + k]), h, l);
        __stcg(&gb_WahH[i], h); __stcg(&gb_WahL[i], l);
        split1(__ldg(&Wattn[gg*(2*HH) + HH + k]), h, l);
        __stcg(&gb_WaeH[i], h); __stcg(&gb_WaeL[i], l);
    }
    for (int i = gtid; i < G3*HH; i += gstr) {
        bf16 h, l;
        split1(__ldg(&Wh0[i]), h, l); __stcg(&gb_Wh0H[i], h); __stcg(&gb_Wh0L[i], l);
        split1(__ldg(&Wh1[i]), h, l); __stcg(&gb_Wh1H[i], h); __stcg(&gb_Wh1L[i], l);
        split1(__ldg(&Wi1[i]), h, l); __stcg(&gb_Wi1H[i], h); __stcg(&gb_Wi1L[i], l);
    }
    for (int i = gtid; i < G3*KX0; i += gstr) {
        bf16 h, l; split1(__ldg(&Wi0[i]), h, l);
        __stcg(&gb_Wi0H[i], h); __stcg(&gb_Wi0L[i], l);
    }
    gsync();

    // ===== phase E: enc_proj (96 M-tiles x 8 N-tiles, K=512) =====
    for (int it = bid; it < 96*8; it += NBLK) {
        int m = it >> 3, n = it & 7;
        gemm_job(sPl,
                 gb_encH + m*64*HH, gb_encL + m*64*HH, HH,
                 gb_WaeH + n*64*HH, gb_WaeL + n*64*HH, HH,
                 g_encproj + m*64*HH + n*64, HH, HH);
    }
    gsync();

    // ===== 12 decode steps =====
    for (int t = 0; t < DECL; t++) {
        // --- PA: query (8Nx2K=16 jobs) + gh0/gh1 (48Nx2K=96 jobs) = 112 jobs, K=256
        for (int it = bid; it < 112; it += NBLK) {
            int col0, s;
            const bf16 *AH, *AL, *WH, *WL;
            if (it < 16) {
                col0 = (it >> 1) * 64; s = it & 1;
                AH = gb_h1H; AL = gb_h1L;
                WH = gb_WahH + col0*HH; WL = gb_WahL + col0*HH;
            } else {
                int jt = it - 16;
                col0 = 512 + (jt >> 1) * 64; s = jt & 1;
                if (col0 < 2048) {
                    AH = gb_h0H; AL = gb_h0L;
                    WH = gb_Wh0H + (col0-512)*HH; WL = gb_Wh0L + (col0-512)*HH;
                } else {
                    AH = gb_h1H; AL = gb_h1L;
                    WH = gb_Wh1H + (col0-2048)*HH; WL = gb_Wh1L + (col0-2048)*HH;
                }
            }
            int k0 = s * 256;
            gemm_job(sPl, AH + k0, AL + k0, HH, WH + k0, WL + k0, HH,
                     g_pre[s] + col0, NPRE, 256);
        }
        gsync();

        // --- PB: scores: job = (b, part6), 16 energies (one per warp); 384 jobs
        for (int it = bid; it < BB*6; it += NBLK) {
            __syncthreads();
            int b = it / 6, part = it % 6;
            float* qs = sBuf;
            float* vs = sBuf + 512;
            float qv = __ldg(&b_attn[tid])
                     + __ldcg(&g_pre[0][b*NPRE + tid])
                     + __ldcg(&g_pre[1][b*NPRE + tid]);
            qs[tid] = qv;
            vs[tid] = __ldg(&v_attn[tid]);
            __syncthreads();
            int e = part*16 + warp;
            const float4* ep4 = reinterpret_cast<const float4*>(g_encproj + (b*EE + e)*HH);
            float ssum = 0.0f;
            #pragma unroll
            for (int i = 0; i < 4; i++) {
                float4 v = __ldcg(&ep4[i*32 + lane]);
                int gg = (i*32 + lane) * 4;
                ssum += fast_tanh(v.x + qs[gg  ]) * vs[gg  ];
                ssum += fast_tanh(v.y + qs[gg+1]) * vs[gg+1];
                ssum += fast_tanh(v.z + qs[gg+2]) * vs[gg+2];
                ssum += fast_tanh(v.w + qs[gg+3]) * vs[gg+3];
            }
            #pragma unroll
            for (int off = 16; off > 0; off >>= 1)
                ssum += __shfl_xor_sync(0xffffffffu, ssum, off);
            if (lane == 0) __stcg(&g_sc[b*EE + e], ssum);
        }
        gsync();

        // --- PC: softmax + ws + assemble x0 : 64 jobs
        for (int it = bid; it < BB; it += NBLK) {
            __syncthreads();
            int b = it;
            float* sc = sBuf;
            if (warp == 0) {
                float s0 = __ldcg(&g_sc[b*EE + lane]);
                float s1 = __ldcg(&g_sc[b*EE + lane + 32]);
                float s2 = __ldcg(&g_sc[b*EE + lane + 64]);
                float m = fmaxf(s0, fmaxf(s1, s2));
                #pragma unroll
                for (int off = 16; off > 0; off >>= 1)
                    m = fmaxf(m, __shfl_xor_sync(0xffffffffu, m, off));
                float p0 = __expf(s0-m), p1 = __expf(s1-m), p2 = __expf(s2-m);
                float sum = p0 + p1 + p2;
                #pragma unroll
                for (int off = 16; off > 0; off >>= 1)
                    sum += __shfl_xor_sync(0xffffffffu, sum, off);
                float inv = 1.0f / sum;
                sc[lane] = p0*inv; sc[lane+32] = p1*inv; sc[lane+64] = p2*inv;
            }
            __syncthreads();
            float acc = 0.0f;
            const float* eb = enc + b*EE*HH + tid;
            #pragma unroll 8
            for (int e = 0; e < EE; e++) acc += sc[e] * __ldg(&eb[e*HH]);
            __stcg(&g_ws[b*HH + tid], acc);
            bf16 h, l; split1(acc, h, l);
            __stcg(&gb_x0H[b*KX0 + FF + tid], h);
            __stcg(&gb_x0L[b*KX0 + FF + tid], l);
            if (tid < FF) {
                float cv = __ldcg(&g_cur[b*FF + tid]);
                split1(cv, h, l);
                __stcg(&gb_x0H[b*KX0 + tid], h);
                __stcg(&gb_x0L[b*KX0 + tid], l);
            }
        }
        gsync();

        // --- PD: gi0 = x0 @ Wi0^T : 24 N-tiles x Ksplit4 {128,128,128,160} = 96 jobs
        for (int it = bid; it < 96; it += NBLK) {
            int col0 = (it >> 2) * 64;
            int s    = it & 3;
            int k0   = s * 128;
            int klen = (s == 3) ? 160 : 128;
            gemm_job(sPl, gb_x0H + k0, gb_x0L + k0, KX0,
                     gb_Wi0H + col0*KX0 + k0, gb_Wi0L + col0*KX0 + k0, KX0,
                     g_gi[s] + col0, G3, klen);
        }
        gsync();

        // --- PE: GRU combine layer 0 -> h0 : 64 jobs
        for (int it = bid; it < BB; it += NBLK) {
            int b = it, j = tid;
            float ir = __ldg(&bi0[j]), iz = __ldg(&bi0[j+HH]), in_ = __ldg(&bi0[j+2*HH]);
            float hr = __ldg(&bh0[j]), hz = __ldg(&bh0[j+HH]), hn  = __ldg(&bh0[j+2*HH]);
            #pragma unroll
            for (int s = 0; s < 4; s++) {
                const float* gi = g_gi[s] + b*G3;
                ir += __ldcg(&gi[j]); iz += __ldcg(&gi[j+HH]); in_ += __ldcg(&gi[j+2*HH]);
            }
            #pragma unroll
            for (int s = 0; s < 2; s++) {
                const float* gh = g_pre[s] + b*NPRE + 512;
                hr += __ldcg(&gh[j]); hz += __ldcg(&gh[j+HH]); hn += __ldcg(&gh[j+2*HH]);
            }
            float r = fast_sigmoid(ir + hr);
            float z = fast_sigmoid(iz + hz);
            float n = fast_tanh(in_ + r * hn);
            float hp = __ldcg(&g_h0[b*HH + j]);
            float h0n = (1.0f - z)*n + z*hp;
            __stcg(&g_h0[b*HH + j], h0n);
            bf16 h, l; split1(h0n, h, l);
            __stcg(&gb_h0H[b*HH + j], h);
            __stcg(&gb_h0L[b*HH + j], l);
        }
        gsync();

        // --- PF: gi1 = h0_new @ Wi1^T : 24 N-tiles x Ksplit4(128) = 96 jobs
        for (int it = bid; it < 96; it += NBLK) {
            int col0 = (it >> 2) * 64;
            int s    = it & 3;
            int k0   = s * 128;
            gemm_job(sPl, gb_h0H + k0, gb_h0L + k0, HH,
                     gb_Wi1H + col0*HH + k0, gb_Wi1L + col0*HH + k0, HH,
                     g_gi[s] + col0, G3, 128);
        }
        gsync();

        // --- PG: GRU combine layer 1 -> h1, fused out-proj + next cur : 64 jobs
        for (int it = bid; it < BB; it += NBLK) {
            __syncthreads();
            int b = it, j = tid;
            float* ho  = sBuf;          // 512
            float* red = sBuf + 512;    // 64 + 4
            float ir = __ldg(&bi1[j]), iz = __ldg(&bi1[j+HH]), in_ = __ldg(&bi1[j+2*HH]);
            float hr = __ldg(&bh1[j]), hz = __ldg(&bh1[j+HH]), hn  = __ldg(&bh1[j+2*HH]);
            #pragma unroll
            for (int s = 0; s < 4; s++) {
                const float* gi = g_gi[s] + b*G3;
                ir += __ldcg(&gi[j]); iz += __ldcg(&gi[j+HH]); in_ += __ldcg(&gi[j+2*HH]);
            }
            #pragma unroll
            for (int s = 0; s < 2; s++) {
                const float* gh = g_pre[s] + b*NPRE + 2048;
                hr += __ldcg(&gh[j]); hz += __ldcg(&gh[j+HH]); hn += __ldcg(&gh[j+2*HH]);
            }
            float r = fast_sigmoid(ir + hr);
            float z = fast_sigmoid(iz + hz);
            float n = fast_tanh(in_ + r * hn);
            float hp = __ldcg(&g_h1[b*HH + j]);
            float h1n = (1.0f - z)*n + z*hp;
            __stcg(&g_h1[b*HH + j], h1n);
            bf16 h, l; split1(h1n, h, l);
            __stcg(&gb_h1H[b*HH + j], h);
            __stcg(&gb_h1L[b*HH + j], l);
            ho[j] = h1n;
            __syncthreads();

            float a0 = 0.f, a1 = 0.f, a2 = 0.f, a3 = 0.f;
            for (int k = tid; k < KOUT; k += 512) {
                float x;
                if (k < HH)          x = ho[k];
                else if (k < 2*HH)   x = __ldcg(&g_ws[b*HH + k - HH]);
                else                 x = __ldcg(&g_cur[b*FF + (k - 2*HH)]);
                a0 += x * __ldg(&W_out[k]);
                a1 += x * __ldg(&W_out[KOUT + k]);
                a2 += x * __ldg(&W_out[2*KOUT + k]);
                a3 += x * __ldg(&W_out[3*KOUT + k]);
            }
            #pragma unroll
            for (int off = 16; off > 0; off >>= 1) {
                a0 += __shfl_xor_sync(0xffffffffu, a0, off);
                a1 += __shfl_xor_sync(0xffffffffu, a1, off);
                a2 += __shfl_xor_sync(0xffffffffu, a2, off);
                a3 += __shfl_xor_sync(0xffffffffu, a3, off);
            }
            if (lane == 0) {
                red[0*16 + warp] = a0; red[1*16 + warp] = a1;
                red[2*16 + warp] = a2; red[3*16 + warp] = a3;
            }
            __syncthreads();
            if (tid < 4) {
                float s = __ldg(&b_out[tid]);
                #pragma unroll
                for (int w = 0; w < 16; w++) s += red[tid*16 + w];
                dout[(b*DECL + t)*TT + tid] = s;
                red[64 + tid] = s;
            }
            __syncthreads();
            if (tid < FF)
                __stcg(&g_cur[b*FF + tid], __ldg(&inputs[(b*DECL + t)*FF + tid]));
            __syncthreads();
            if (tid < TT)
                __stcg(&g_cur[b*FF + __ldg(&tind[tid])], red[64 + tid]);
        }
        if (t < DECL - 1) gsync();
    }
}

// ---------------- launch ----------------
extern "C" void kernel_launch(void* const* d_in, const int* in_sizes, int n_in,
                              void* d_out, int out_size)
{
    const float* inputs   = (const float*)d_in[0];
    const float* hidden   = (const float*)d_in[1];
    const float* enc      = (const float*)d_in[2];
    const int*   tindices = (const int*)  d_in[3];
    const float* W_attn   = (const float*)d_in[4];
    const float* b_attn   = (const float*)d_in[5];
    const float* v_attn   = (const float*)d_in[6];
    const float* Wi0      = (const float*)d_in[7];
    const float* Wh0      = (const float*)d_in[8];
    const float* bi0      = (const float*)d_in[9];
    const float* bh0      = (const float*)d_in[10];
    const float* Wi1      = (const float*)d_in[11];
    const float* Wh1      = (const float*)d_in[12];
    const float* bi1      = (const float*)d_in[13];
    const float* bh1      = (const float*)d_in[14];
    const float* W_out    = (const float*)d_in[15];
    const float* b_out    = (const float*)d_in[16];
    float* out = (float*)d_out;

    static bool attr_set = false;
    if (!attr_set) {
        cudaFuncSetAttribute(k_decoder, cudaFuncAttributeMaxDynamicSharedMemorySize, SMEM_DYN);
        attr_set = true;
    }
    k_decoder<<<NBLK, 512, SMEM_DYN>>>(inputs, hidden, enc, tindices,
                                       W_attn, b_attn, v_attn,
                                       Wi0, Wh0, bi0, bh0,
                                       Wi1, Wh1, bi1, bh1,
                                       W_out, b_out, out);
}

// round 17
// speedup vs baseline: 1.2709x; 1.0921x over previous
#include <cuda_runtime.h>
#include <cuda_bf16.h>
#include <math.h>

typedef unsigned int uint;
typedef __nv_bfloat16 bf16;

#define BB   64
#define DECL 12
#define FF   32
#define HH   512
#define EE   96
#define TT   4
#define G3   1536
#define NPRE 3584   /* 512 (query) + 1536 (gh0) + 1536 (gh1) */
#define KX0  544    /* F + H */
#define KOUT 1056   /* 2H + F */
#define NBLK 148
#define SRB  72     /* bf16 smem plane row stride */
#define PLANE (64*SRB)          /* 4608 elems = 9216 B */
#define SMEM_DYN (8*PLANE*2 + 1152*4)

// ---------------- fp32 scratch ----------------
__device__ __align__(16) float g_encproj[BB*EE*HH];
__device__ __align__(16) float g_h0[BB*HH];
__device__ __align__(16) float g_h1[BB*HH];
__device__ __align__(16) float g_cur[BB*FF];
__device__ __align__(16) float g_pre[2][BB*NPRE];     // K-split x2: query|gh0|gh1
__device__ __align__(16) float g_gi[4][BB*G3];        // K-split x4 for gi
__device__ __align__(16) float g_ws[BB*HH];

// ---------------- bf16 hi/lo planes ----------------
__device__ __align__(16) bf16 gb_encH[BB*EE*HH], gb_encL[BB*EE*HH];
__device__ __align__(16) bf16 gb_WaeH[HH*HH],    gb_WaeL[HH*HH];
__device__ __align__(16) bf16 gb_WahH[HH*HH],    gb_WahL[HH*HH];
__device__ __align__(16) bf16 gb_Wh0H[G3*HH],    gb_Wh0L[G3*HH];
__device__ __align__(16) bf16 gb_Wh1H[G3*HH],    gb_Wh1L[G3*HH];
__device__ __align__(16) bf16 gb_Wi0H[G3*KX0],   gb_Wi0L[G3*KX0];
__device__ __align__(16) bf16 gb_Wi1H[G3*HH],    gb_Wi1L[G3*HH];
__device__ __align__(16) bf16 gb_h0H[BB*HH],     gb_h0L[BB*HH];
__device__ __align__(16) bf16 gb_h1H[BB*HH],     gb_h1L[BB*HH];
__device__ __align__(16) bf16 gb_x0H[BB*KX0],    gb_x0L[BB*KX0];

__device__ unsigned g_bar_cnt = 0;
__device__ unsigned g_bar_gen = 0;

// ---------------- helpers ----------------
__device__ __forceinline__ float fast_sigmoid(float x) {
    return 1.0f / (1.0f + __expf(-x));
}
__device__ __forceinline__ float fast_tanh(float x) {
    float e = __expf(-2.0f * fabsf(x));
    float t = (1.0f - e) / (1.0f + e);
    return copysignf(t, x);
}
__device__ __forceinline__ float tanha(float x) {   // scores only
    float y; asm("tanh.approx.f32 %0, %1;" : "=f"(y) : "f"(x)); return y;
}
__device__ __forceinline__ void split1(float x, bf16 &h, bf16 &l) {
    h = __float2bfloat16(x);
    l = __float2bfloat16(x - __bfloat162float(h));
}
__device__ __forceinline__ void mma16816(float* d, const uint* a, uint b0, uint b1) {
    asm volatile(
        "mma.sync.aligned.m16n8k16.row.col.f32.bf16.bf16.f32 "
        "{%0,%1,%2,%3},{%4,%5,%6,%7},{%8,%9},{%0,%1,%2,%3};"
        : "+f"(d[0]), "+f"(d[1]), "+f"(d[2]), "+f"(d[3])
        : "r"(a[0]), "r"(a[1]), "r"(a[2]), "r"(a[3]), "r"(b0), "r"(b1));
}
__device__ __forceinline__ void ldsm4(uint* r, uint addr) {
    asm volatile("ldmatrix.sync.aligned.m8n8.x4.shared.b16 {%0,%1,%2,%3}, [%4];"
                 : "=r"(r[0]), "=r"(r[1]), "=r"(r[2]), "=r"(r[3]) : "r"(addr));
}
__device__ __forceinline__ void cpa16(bf16* dst, const bf16* src) {
    uint d = (uint)__cvta_generic_to_shared(dst);
    asm volatile("cp.async.cg.shared.global [%0], [%1], 16;" :: "r"(d), "l"(src) : "memory");
}

// grid barrier — proven R13 implementation (threadfence + volatile spin)
__device__ __forceinline__ void gsync() {
    __syncthreads();
    if (threadIdx.x == 0) {
        __threadfence();
        unsigned gen = *((volatile unsigned*)&g_bar_gen);
        if (atomicAdd(&g_bar_cnt, 1u) == (unsigned)(NBLK - 1)) {
            g_bar_cnt = 0;
            __threadfence();
            *((volatile unsigned*)&g_bar_gen) = gen + 1u;
        } else {
            while (*((volatile unsigned*)&g_bar_gen) == gen) { }
        }
    }
    __syncthreads();
}

// ---------------- cp.async double-buffered bf16x3 TC GEMM (ldmatrix) ----------------
// C[64][64] = A[64][klen] @ W[64][klen]^T ; klen % 32 == 0; 512 threads.
__device__ __forceinline__ void gemm_job(
    bf16* __restrict__ sPl,
    const bf16* __restrict__ AH, const bf16* __restrict__ AL, int lda,
    const bf16* __restrict__ WH, const bf16* __restrict__ WL, int ldw,
    float* __restrict__ C, int ldc, int klen)
{
    const int tid  = threadIdx.x;
    const int warp = tid >> 5, lane = tid & 31;
    const int rt = warp >> 2, ct = warp & 3;       // warp tile 16x16
    const int q  = (lane & 3) << 1;
    const int srow = tid >> 3, sc8 = (tid & 7) << 3;
    const int a_off = ((rt*16 + (((lane>>3)&1)<<3) + (lane&7)) * SRB
                       + ((lane>>4)<<3)) * 2;
    const int b_off = ((ct*16 + ((lane>>4)<<3) + (lane&7)) * SRB
                       + (((lane>>3)&1)<<3)) * 2;
    float d[2][4] = {};
    const int nch = (klen + 63) >> 6;

    {
        if (sc8 < klen) {
            cpa16(&sPl[0*PLANE + srow*SRB + sc8], &AH[srow*lda + sc8]);
            cpa16(&sPl[1*PLANE + srow*SRB + sc8], &AL[srow*lda + sc8]);
            cpa16(&sPl[2*PLANE + srow*SRB + sc8], &WH[srow*ldw + sc8]);
            cpa16(&sPl[3*PLANE + srow*SRB + sc8], &WL[srow*ldw + sc8]);
        }
        asm volatile("cp.async.commit_group;" ::: "memory");
    }

    for (int c = 0; c < nch; c++) {
        const int buf = c & 1;
        if (c + 1 < nch) {
            const int k1 = (c + 1) << 6;
            const int rem1 = klen - k1;
            bf16* b1 = sPl + (buf ^ 1)*4*PLANE;
            if (sc8 < rem1) {
                const int off = k1 + sc8;
                cpa16(&b1[0*PLANE + srow*SRB + sc8], &AH[srow*lda + off]);
                cpa16(&b1[1*PLANE + srow*SRB + sc8], &AL[srow*lda + off]);
                cpa16(&b1[2*PLANE + srow*SRB + sc8], &WH[srow*ldw + off]);
                cpa16(&b1[3*PLANE + srow*SRB + sc8], &WL[srow*ldw + off]);
            }
            asm volatile("cp.async.commit_group;" ::: "memory");
            asm volatile("cp.async.wait_group 1;" ::: "memory");
        } else {
            asm volatile("cp.async.wait_group 0;" ::: "memory");
        }
        __syncthreads();

        const bf16* base = sPl + buf*4*PLANE;
        const uint sbase = (uint)__cvta_generic_to_shared(base);
        const uint aAH = sbase + a_off;
        const uint aAL = aAH + PLANE*2;
        const uint aWH = sbase + 2*PLANE*2 + b_off;
        const uint aWL = aWH + PLANE*2;
        const int rem = klen - (c << 6);
        #pragma unroll
        for (int ks = 0; ks < 64; ks += 16) {
            if (ks < rem) {
                uint aH[4], aL[4], bh[4], bl[4];
                ldsm4(aH, aAH + ks*2);
                ldsm4(aL, aAL + ks*2);
                ldsm4(bh, aWH + ks*2);
                ldsm4(bl, aWL + ks*2);
                mma16816(d[0], aH, bh[0], bh[1]);
                mma16816(d[1], aH, bh[2], bh[3]);
                mma16816(d[0], aH, bl[0], bl[1]);
                mma16816(d[1], aH, bl[2], bl[3]);
                mma16816(d[0], aL, bh[0], bh[1]);
                mma16816(d[1], aL, bh[2], bh[3]);
            }
        }
        __syncthreads();
    }

    const int g = lane >> 2;
    const int r0 = rt*16 + g;
    #pragma unroll
    for (int nt = 0; nt < 2; nt++) {
        const int c0 = ct*16 + nt*8 + q;
        __stcg(reinterpret_cast<float2*>(&C[r0*ldc + c0]),       make_float2(d[nt][0], d[nt][1]));
        __stcg(reinterpret_cast<float2*>(&C[(r0 + 8)*ldc + c0]), make_float2(d[nt][2], d[nt][3]));
    }
}

// ---------------- the whole decoder, persistent ----------------
__global__ __launch_bounds__(512, 1) void k_decoder(
    const float* __restrict__ inputs, const float* __restrict__ hidden,
    const float* __restrict__ enc,    const int* __restrict__ tind,
    const float* __restrict__ Wattn,  const float* __restrict__ b_attn,
    const float* __restrict__ v_attn,
    const float* __restrict__ Wi0, const float* __restrict__ Wh0,
    const float* __restrict__ bi0, const float* __restrict__ bh0,
    const float* __restrict__ Wi1, const float* __restrict__ Wh1,
    const float* __restrict__ bi1, const float* __restrict__ bh1,
    const float* __restrict__ W_out, const float* __restrict__ b_out,
    float* __restrict__ dout)
{
    extern __shared__ __align__(16) char smem_raw[];
    bf16*  sPl  = reinterpret_cast<bf16*>(smem_raw);
    float* sBuf = reinterpret_cast<float*>(smem_raw + 8*PLANE*2);

    const int bid  = blockIdx.x;
    const int tid  = threadIdx.x;
    const int warp = tid >> 5, lane = tid & 31;   // 16 warps
    const int gtid = bid*512 + tid;
    const int gstr = NBLK*512;

    // ===== init: copies + one-time bf16 splits =====
    for (int i = gtid; i < BB*HH; i += gstr) {
        float h0v = __ldg(&hidden[i]);
        float h1v = __ldg(&hidden[BB*HH + i]);
        __stcg(&g_h0[i], h0v);
        __stcg(&g_h1[i], h1v);
        bf16 hh, hl;
        split1(h0v, hh, hl); __stcg(&gb_h0H[i], hh); __stcg(&gb_h0L[i], hl);
        split1(h1v, hh, hl); __stcg(&gb_h1H[i], hh); __stcg(&gb_h1L[i], hl);
    }
    for (int i = gtid; i < BB*FF; i += gstr) {
        int b = i >> 5, f = i & 31;
        __stcg(&g_cur[i], __ldg(&inputs[b*DECL*FF + f]));
    }
    for (int i = gtid; i < BB*EE*HH; i += gstr) {
        bf16 h, l; split1(__ldg(&enc[i]), h, l);
        __stcg(&gb_encH[i], h); __stcg(&gb_encL[i], l);
    }
    for (int i = gtid; i < HH*HH; i += gstr) {
        int gg = i >> 9, k = i & 511;
        bf16 h, l;
        split1(__ldg(&Wattn[gg*(2*HH) + k]), h, l);
        __stcg(&gb_WahH[i], h); __stcg(&gb_WahL[i], l);
        split1(__ldg(&Wattn[gg*(2*HH) + HH + k]), h, l);
        __stcg(&gb_WaeH[i], h); __stcg(&gb_WaeL[i], l);
    }
    for (int i = gtid; i < G3*HH; i += gstr) {
        bf16 h, l;
        split1(__ldg(&Wh0[i]), h, l); __stcg(&gb_Wh0H[i], h); __stcg(&gb_Wh0L[i], l);
        split1(__ldg(&Wh1[i]), h, l); __stcg(&gb_Wh1H[i], h); __stcg(&gb_Wh1L[i], l);
        split1(__ldg(&Wi1[i]), h, l); __stcg(&gb_Wi1H[i], h); __stcg(&gb_Wi1L[i], l);
    }
    for (int i = gtid; i < G3*KX0; i += gstr) {
        bf16 h, l; split1(__ldg(&Wi0[i]), h, l);
        __stcg(&gb_Wi0H[i], h); __stcg(&gb_Wi0L[i], l);
    }
    gsync();

    // ===== phase E: enc_proj (96 M-tiles x 8 N-tiles, K=512) =====
    for (int it = bid; it < 96*8; it += NBLK) {
        int m = it >> 3, n = it & 7;
        gemm_job(sPl,
                 gb_encH + m*64*HH, gb_encL + m*64*HH, HH,
                 gb_WaeH + n*64*HH, gb_WaeL + n*64*HH, HH,
                 g_encproj + m*64*HH + n*64, HH, HH);
    }
    gsync();

    // ===== 12 decode steps =====
    for (int t = 0; t < DECL; t++) {
        // --- PA: query (16) + gh0/gh1 (96) = 112 jobs, K=256
        for (int it = bid; it < 112; it += NBLK) {
            int col0, s;
            const bf16 *AH, *AL, *WH, *WL;
            if (it < 16) {
                col0 = (it >> 1) * 64; s = it & 1;
                AH = gb_h1H; AL = gb_h1L;
                WH = gb_WahH + col0*HH; WL = gb_WahL + col0*HH;
            } else {
                int jt = it - 16;
                col0 = 512 + (jt >> 1) * 64; s = jt & 1;
                if (col0 < 2048) {
                    AH = gb_h0H; AL = gb_h0L;
                    WH = gb_Wh0H + (col0-512)*HH; WL = gb_Wh0L + (col0-512)*HH;
                } else {
                    AH = gb_h1H; AL = gb_h1L;
                    WH = gb_Wh1H + (col0-2048)*HH; WL = gb_Wh1L + (col0-2048)*HH;
                }
            }
            int k0 = s * 256;
            gemm_job(sPl, AH + k0, AL + k0, HH, WH + k0, WL + k0, HH,
                     g_pre[s] + col0, NPRE, 256);
        }
        gsync();

        // --- PB': scores + softmax + ws + x0, one block per b : 64 jobs
        for (int it = bid; it < BB; it += NBLK) {
            __syncthreads();
            const int b = it;
            float* qs = sBuf;          // 512
            float* vs = sBuf + 512;    // 512
            float* sc = sBuf + 1024;   // 96
            float qv = __ldg(&b_attn[tid])
                     + __ldcg(&g_pre[0][b*NPRE + tid])
                     + __ldcg(&g_pre[1][b*NPRE + tid]);
            qs[tid] = qv;
            vs[tid] = __ldg(&v_attn[tid]);
            __syncthreads();

            // 96 energies: warp w -> e = w + 16*j, j=0..5 (tanh.approx)
            for (int j = 0; j < 6; j++) {
                int e = warp + 16*j;
                const float4* ep4 = reinterpret_cast<const float4*>(g_encproj + (b*EE + e)*HH);
                float ssum = 0.0f;
                #pragma unroll
                for (int i = 0; i < 4; i++) {
                    float4 v = __ldcg(&ep4[i*32 + lane]);
                    int gg = (i*32 + lane) * 4;
                    ssum += tanha(v.x + qs[gg  ]) * vs[gg  ];
                    ssum += tanha(v.y + qs[gg+1]) * vs[gg+1];
                    ssum += tanha(v.z + qs[gg+2]) * vs[gg+2];
                    ssum += tanha(v.w + qs[gg+3]) * vs[gg+3];
                }
                #pragma unroll
                for (int off = 16; off > 0; off >>= 1)
                    ssum += __shfl_xor_sync(0xffffffffu, ssum, off);
                if (lane == 0) sc[e] = ssum;
            }
            __syncthreads();

            // softmax over 96 (warp 0, in smem)
            if (warp == 0) {
                float s0 = sc[lane], s1 = sc[lane+32], s2 = sc[lane+64];
                float m = fmaxf(s0, fmaxf(s1, s2));
                #pragma unroll
                for (int off = 16; off > 0; off >>= 1)
                    m = fmaxf(m, __shfl_xor_sync(0xffffffffu, m, off));
                float p0 = __expf(s0-m), p1 = __expf(s1-m), p2 = __expf(s2-m);
                float sum = p0 + p1 + p2;
                #pragma unroll
                for (int off = 16; off > 0; off >>= 1)
                    sum += __shfl_xor_sync(0xffffffffu, sum, off);
                float inv = 1.0f / sum;
                sc[lane] = p0*inv; sc[lane+32] = p1*inv; sc[lane+64] = p2*inv;
            }
            __syncthreads();

            // ws + x0 planes
            float acc = 0.0f;
            const float* eb = enc + b*EE*HH + tid;
            #pragma unroll 8
            for (int e = 0; e < EE; e++) acc += sc[e] * __ldg(&eb[e*HH]);
            __stcg(&g_ws[b*HH + tid], acc);
            bf16 h, l; split1(acc, h, l);
            __stcg(&gb_x0H[b*KX0 + FF + tid], h);
            __stcg(&gb_x0L[b*KX0 + FF + tid], l);
            if (tid < FF) {
                float cv = __ldcg(&g_cur[b*FF + tid]);
                split1(cv, h, l);
                __stcg(&gb_x0H[b*KX0 + tid], h);
                __stcg(&gb_x0L[b*KX0 + tid], l);
            }
        }
        gsync();

        // --- PD: gi0 = x0 @ Wi0^T : 24 N-tiles x Ksplit4 {128,128,128,160} = 96 jobs
        for (int it = bid; it < 96; it += NBLK) {
            int col0 = (it >> 2) * 64;
            int s    = it & 3;
            int k0   = s * 128;
            int klen = (s == 3) ? 160 : 128;
            gemm_job(sPl, gb_x0H + k0, gb_x0L + k0, KX0,
                     gb_Wi0H + col0*KX0 + k0, gb_Wi0L + col0*KX0 + k0, KX0,
                     g_gi[s] + col0, G3, klen);
        }
        gsync();

        // --- PE: GRU combine layer 0 -> h0 : 64 jobs
        for (int it = bid; it < BB; it += NBLK) {
            int b = it, j = tid;
            float ir = __ldg(&bi0[j]), iz = __ldg(&bi0[j+HH]), in_ = __ldg(&bi0[j+2*HH]);
            float hr = __ldg(&bh0[j]), hz = __ldg(&bh0[j+HH]), hn  = __ldg(&bh0[j+2*HH]);
            #pragma unroll
            for (int s = 0; s < 4; s++) {
                const float* gi = g_gi[s] + b*G3;
                ir += __ldcg(&gi[j]); iz += __ldcg(&gi[j+HH]); in_ += __ldcg(&gi[j+2*HH]);
            }
            #pragma unroll
            for (int s = 0; s < 2; s++) {
                const float* gh = g_pre[s] + b*NPRE + 512;
                hr += __ldcg(&gh[j]); hz += __ldcg(&gh[j+HH]); hn += __ldcg(&gh[j+2*HH]);
            }
            float r = fast_sigmoid(ir + hr);
            float z = fast_sigmoid(iz + hz);
            float n = fast_tanh(in_ + r * hn);
            float hp = __ldcg(&g_h0[b*HH + j]);
            float h0n = (1.0f - z)*n + z*hp;
            __stcg(&g_h0[b*HH + j], h0n);
            bf16 h, l; split1(h0n, h, l);
            __stcg(&gb_h0H[b*HH + j], h);
            __stcg(&gb_h0L[b*HH + j], l);
        }
        gsync();

        // --- PF: gi1 = h0_new @ Wi1^T : 24 N-tiles x Ksplit4(128) = 96 jobs
        for (int it = bid; it < 96; it += NBLK) {
            int col0 = (it >> 2) * 64;
            int s    = it & 3;
            int k0   = s * 128;
            gemm_job(sPl, gb_h0H + k0, gb_h0L + k0, HH,
                     gb_Wi1H + col0*HH + k0, gb_Wi1L + col0*HH + k0, HH,
                     g_gi[s] + col0, G3, 128);
        }
        gsync();

        // --- PG: GRU combine layer 1 -> h1, fused out-proj + next cur : 64 jobs
        for (int it = bid; it < BB; it += NBLK) {
            __syncthreads();
            int b = it, j = tid;
            float* ho  = sBuf;          // 512
            float* red = sBuf + 512;    // 64 + 4
            float ir = __ldg(&bi1[j]), iz = __ldg(&bi1[j+HH]), in_ = __ldg(&bi1[j+2*HH]);
            float hr = __ldg(&bh1[j]), hz = __ldg(&bh1[j+HH]), hn  = __ldg(&bh1[j+2*HH]);
            #pragma unroll
            for (int s = 0; s < 4; s++) {
                const float* gi = g_gi[s] + b*G3;
                ir += __ldcg(&gi[j]); iz += __ldcg(&gi[j+HH]); in_ += __ldcg(&gi[j+2*HH]);
            }
            #pragma unroll
            for (int s = 0; s < 2; s++) {
                const float* gh = g_pre[s] + b*NPRE + 2048;
                hr += __ldcg(&gh[j]); hz += __ldcg(&gh[j+HH]); hn += __ldcg(&gh[j+2*HH]);
            }
            float r = fast_sigmoid(ir + hr);
            float z = fast_sigmoid(iz + hz);
            float n = fast_tanh(in_ + r * hn);
            float hp = __ldcg(&g_h1[b*HH + j]);
            float h1n = (1.0f - z)*n + z*hp;
            __stcg(&g_h1[b*HH + j], h1n);
            bf16 h, l; split1(h1n, h, l);
            __stcg(&gb_h1H[b*HH + j], h);
            __stcg(&gb_h1L[b*HH + j], l);
            ho[j] = h1n;
            __syncthreads();

            float a0 = 0.f, a1 = 0.f, a2 = 0.f, a3 = 0.f;
            for (int k = tid; k < KOUT; k += 512) {
                float x;
                if (k < HH)          x = ho[k];
                else if (k < 2*HH)   x = __ldcg(&g_ws[b*HH + k - HH]);
                else                 x = __ldcg(&g_cur[b*FF + (k - 2*HH)]);
                a0 += x * __ldg(&W_out[k]);
                a1 += x * __ldg(&W_out[KOUT + k]);
                a2 += x * __ldg(&W_out[2*KOUT + k]);
                a3 += x * __ldg(&W_out[3*KOUT + k]);
            }
            #pragma unroll
            for (int off = 16; off > 0; off >>= 1) {
                a0 += __shfl_xor_sync(0xffffffffu, a0, off);
                a1 += __shfl_xor_sync(0xffffffffu, a1, off);
                a2 += __shfl_xor_sync(0xffffffffu, a2, off);
                a3 += __shfl_xor_sync(0xffffffffu, a3, off);
            }
            if (lane == 0) {
                red[0*16 + warp] = a0; red[1*16 + warp] = a1;
                red[2*16 + warp] = a2; red[3*16 + warp] = a3;
            }
            __syncthreads();
            if (tid < 4) {
                float s = __ldg(&b_out[tid]);
                #pragma unroll
                for (int w = 0; w < 16; w++) s += red[tid*16 + w];
                dout[(b*DECL + t)*TT + tid] = s;
                red[64 + tid] = s;
            }
            __syncthreads();
            if (tid < FF)
                __stcg(&g_cur[b*FF + tid], __ldg(&inputs[(b*DECL + t)*FF + tid]));
            __syncthreads();
            if (tid < TT)
                __stcg(&g_cur[b*FF + __ldg(&tind[tid])], red[64 + tid]);
        }
        if (t < DECL - 1) gsync();
    }
}

// ---------------- launch ----------------
extern "C" void kernel_launch(void* const* d_in, const int* in_sizes, int n_in,
                              void* d_out, int out_size)
{
    const float* inputs   = (const float*)d_in[0];
    const float* hidden   = (const float*)d_in[1];
    const float* enc      = (const float*)d_in[2];
    const int*   tindices = (const int*)  d_in[3];
    const float* W_attn   = (const float*)d_in[4];
    const float* b_attn   = (const float*)d_in[5];
    const float* v_attn   = (const float*)d_in[6];
    const float* Wi0      = (const float*)d_in[7];
    const float* Wh0      = (const float*)d_in[8];
    const float* bi0      = (const float*)d_in[9];
    const float* bh0      = (const float*)d_in[10];
    const float* Wi1      = (const float*)d_in[11];
    const float* Wh1      = (const float*)d_in[12];
    const float* bi1      = (const float*)d_in[13];
    const float* bh1      = (const float*)d_in[14];
    const float* W_out    = (const float*)d_in[15];
    const float* b_out    = (const float*)d_in[16];
    float* out = (float*)d_out;

    static bool attr_set = false;
    if (!attr_set) {
        cudaFuncSetAttribute(k_decoder, cudaFuncAttributeMaxDynamicSharedMemorySize, SMEM_DYN);
        attr_set = true;
    }
    k_decoder<<<NBLK, 512, SMEM_DYN>>>(inputs, hidden, enc, tindices,
                                       W_attn, b_attn, v_attn,
                                       Wi0, Wh0, bi0, bh0,
                                       Wi1, Wh1, bi1, bh1,
                                       W_out, b_out, out);
}